// round 1
// baseline (speedup 1.0000x reference)
#include <cuda_runtime.h>
#include <math.h>

#define NN 4096
#define EE 65536
#define IND 128
#define HD 256

// ---------------- scratch (static device globals; no allocation) -------------
__device__ float g_h[NN * HD];
__device__ float g_t1[NN * HD];
__device__ float g_gcn[NN * HD];
__device__ float g_qkv[NN * 3 * HD];
__device__ float g_att[NN * HD];
__device__ float g_out[NN * HD];
__device__ float g_ffn1[NN * 2 * HD];
__device__ float g_a2[NN * HD];
__device__ float g_delta[(size_t)NN * NN];
__device__ float g_deg[NN];
__device__ float g_dinv[NN];

// ---------------- generic NT GEMM: C = act(A @ B^T + bias + s1*R1 + s2*R2) ---
// A: [M,K] row-major, B: [N,K] row-major, C/R1/R2: [M,N]
// tile 64x64xBK16, 128 threads, 4x8 micro-tile
template <bool RELU>
__global__ void __launch_bounds__(128) gemm_nt(
    const float* __restrict__ A, const float* __restrict__ B,
    const float* __restrict__ bias, float* __restrict__ C,
    int M, int N, int K,
    const float* __restrict__ R1, float s1,
    const float* __restrict__ R2, float s2)
{
    const int bm = blockIdx.y * 64;
    const int bn = blockIdx.x * 64;
    __shared__ float As[16][68];
    __shared__ float Bs[16][68];

    const int tid = threadIdx.x;
    const int tr = tid >> 3;      // 0..15 -> rows tr*4..+3
    const int tc = tid & 7;       // 0..7  -> cols tc*8..+7
    const int r0 = tr * 4;
    const int c0 = tc * 8;

    float acc[4][8];
#pragma unroll
    for (int i = 0; i < 4; i++)
#pragma unroll
        for (int j = 0; j < 8; j++) acc[i][j] = 0.f;

    for (int k0 = 0; k0 < K; k0 += 16) {
        // cooperative load: 64x16 per operand, 2 float4 per thread per operand
#pragma unroll
        for (int t = 0; t < 2; t++) {
            int idx = tid + t * 128;         // 0..255
            int m  = idx >> 2;               // 0..63
            int kk = (idx & 3) << 2;         // 0,4,8,12
            float4 av = *(const float4*)&A[(size_t)(bm + m) * K + k0 + kk];
            As[kk + 0][m] = av.x; As[kk + 1][m] = av.y;
            As[kk + 2][m] = av.z; As[kk + 3][m] = av.w;
            float4 bv = *(const float4*)&B[(size_t)(bn + m) * K + k0 + kk];
            Bs[kk + 0][m] = bv.x; Bs[kk + 1][m] = bv.y;
            Bs[kk + 2][m] = bv.z; Bs[kk + 3][m] = bv.w;
        }
        __syncthreads();
#pragma unroll
        for (int k = 0; k < 16; k++) {
            float4 a4 = *(const float4*)&As[k][r0];
            float4 b40 = *(const float4*)&Bs[k][c0];
            float4 b41 = *(const float4*)&Bs[k][c0 + 4];
            float a[4] = {a4.x, a4.y, a4.z, a4.w};
            float b[8] = {b40.x, b40.y, b40.z, b40.w, b41.x, b41.y, b41.z, b41.w};
#pragma unroll
            for (int i = 0; i < 4; i++)
#pragma unroll
                for (int j = 0; j < 8; j++) acc[i][j] += a[i] * b[j];
        }
        __syncthreads();
    }

#pragma unroll
    for (int i = 0; i < 4; i++) {
        int row = bm + r0 + i;
#pragma unroll
        for (int j = 0; j < 8; j++) {
            int col = bn + c0 + j;
            float v = acc[i][j];
            if (bias) v += bias[col];
            if (R1) v += s1 * R1[(size_t)row * N + col];
            if (R2) v += s2 * R2[(size_t)row * N + col];
            if (RELU) v = fmaxf(v, 0.f);
            C[(size_t)row * N + col] = v;
        }
    }
}

// ---------------- GCN helpers ----------------
__global__ void deg_init_k(float* deg) {
    int i = blockIdx.x * blockDim.x + threadIdx.x;
    if (i < NN) deg[i] = 1.0f;  // self loop
}
__global__ void deg_edge_k(const int* __restrict__ dst, float* deg) {
    int e = blockIdx.x * blockDim.x + threadIdx.x;
    if (e < EE) atomicAdd(&deg[dst[e]], 1.0f);
}
__global__ void dinv_k(const float* __restrict__ deg, float* dinv) {
    int i = blockIdx.x * blockDim.x + threadIdx.x;
    if (i < NN) dinv[i] = rsqrtf(deg[i]);
}
// out[i,c] = dinv[i]^2 * t1[i,c] + b[c]   (self-loop term + bias)
__global__ void gcn_init_k(const float* __restrict__ t1, const float* __restrict__ dinv,
                           const float* __restrict__ b, float* __restrict__ out) {
    int i = blockIdx.x;
    int c = threadIdx.x;
    float di = dinv[i];
    out[(size_t)i * HD + c] = di * di * t1[(size_t)i * HD + c] + b[c];
}
// one block per edge, 256 channels
__global__ void gcn_edge_k(const float* __restrict__ t1, const int* __restrict__ src,
                           const int* __restrict__ dst, const float* __restrict__ dinv,
                           float* __restrict__ out) {
    int e = blockIdx.x;
    int c = threadIdx.x;
    int s = src[e], d = dst[e];
    float coef = dinv[s] * dinv[d];
    atomicAdd(&out[(size_t)d * HD + c], coef * t1[(size_t)s * HD + c]);
}

// ---------------- flash attention (fp32, 4 heads, d=64) ----------------
// grid (NN/64, HEADS), 128 threads; 64-query block, 32-key tiles, online softmax
__device__ __forceinline__ float grp_max8(float v) {
    v = fmaxf(v, __shfl_xor_sync(0xffffffffu, v, 1));
    v = fmaxf(v, __shfl_xor_sync(0xffffffffu, v, 2));
    v = fmaxf(v, __shfl_xor_sync(0xffffffffu, v, 4));
    return v;
}
__device__ __forceinline__ float grp_sum8(float v) {
    v += __shfl_xor_sync(0xffffffffu, v, 1);
    v += __shfl_xor_sync(0xffffffffu, v, 2);
    v += __shfl_xor_sync(0xffffffffu, v, 4);
    return v;
}

__global__ void __launch_bounds__(128) attn_kernel(const float* __restrict__ qkv,
                                                   float* __restrict__ out)
{
    const int n0 = blockIdx.x * 64;
    const int hh = blockIdx.y;
    __shared__ float Qs[64][68];  // [d][r], q pre-scaled
    __shared__ float Ks[64][36];  // [d][c]
    __shared__ float Vs[32][68];  // [c][d]
    __shared__ float Ps[64][37];  // [r][c]

    const int tid = threadIdx.x;
    const int tr = tid >> 3;        // 0..15 -> rows tr*4..+3
    const int tc = tid & 7;         // 0..7
    const int r0 = tr * 4;
    const int c0 = tc * 4;          // key cols for S
    const int d0 = tc * 8;          // output dims

    // load Q (scaled by 1/sqrt(64))
    for (int idx = tid; idx < 64 * 64; idx += 128) {
        int r = idx >> 6, d = idx & 63;
        Qs[d][r] = qkv[(size_t)(n0 + r) * 768 + hh * 64 + d] * 0.125f;
    }

    float O[4][8];
    float m[4], l[4];
#pragma unroll
    for (int i = 0; i < 4; i++) {
        m[i] = -1e30f; l[i] = 0.f;
#pragma unroll
        for (int j = 0; j < 8; j++) O[i][j] = 0.f;
    }

    for (int j0 = 0; j0 < NN; j0 += 32) {
        // load K,V tile
        for (int idx = tid; idx < 32 * 64; idx += 128) {
            int c = idx >> 6, d = idx & 63;
            Ks[d][c] = qkv[(size_t)(j0 + c) * 768 + 256 + hh * 64 + d];
            Vs[c][d] = qkv[(size_t)(j0 + c) * 768 + 512 + hh * 64 + d];
        }
        __syncthreads();

        // S = Q K^T  (4x4 per thread)
        float s[4][4];
#pragma unroll
        for (int i = 0; i < 4; i++)
#pragma unroll
            for (int j = 0; j < 4; j++) s[i][j] = 0.f;
#pragma unroll 8
        for (int k = 0; k < 64; k++) {
            float4 a4 = *(const float4*)&Qs[k][r0];
            float4 b4 = *(const float4*)&Ks[k][c0];
            float a[4] = {a4.x, a4.y, a4.z, a4.w};
            float b[4] = {b4.x, b4.y, b4.z, b4.w};
#pragma unroll
            for (int i = 0; i < 4; i++)
#pragma unroll
                for (int j = 0; j < 4; j++) s[i][j] += a[i] * b[j];
        }

        // online softmax per row (row group = 8 consecutive lanes)
#pragma unroll
        for (int i = 0; i < 4; i++) {
            float tm = fmaxf(fmaxf(s[i][0], s[i][1]), fmaxf(s[i][2], s[i][3]));
            tm = grp_max8(tm);
            float mn = fmaxf(m[i], tm);
            float corr = __expf(m[i] - mn);
            float ls = 0.f;
#pragma unroll
            for (int j = 0; j < 4; j++) {
                s[i][j] = __expf(s[i][j] - mn);
                ls += s[i][j];
            }
            ls = grp_sum8(ls);
            l[i] = l[i] * corr + ls;
            m[i] = mn;
#pragma unroll
            for (int j = 0; j < 8; j++) O[i][j] *= corr;
#pragma unroll
            for (int j = 0; j < 4; j++) Ps[r0 + i][c0 + j] = s[i][j];
        }
        __syncwarp();  // P rows are produced within each warp's own row-groups

        // O += P V   (4 rows x 8 dims per thread)
#pragma unroll 4
        for (int c = 0; c < 32; c++) {
            float p[4];
#pragma unroll
            for (int i = 0; i < 4; i++) p[i] = Ps[r0 + i][c];
            float4 v0 = *(const float4*)&Vs[c][d0];
            float4 v1 = *(const float4*)&Vs[c][d0 + 4];
            float v[8] = {v0.x, v0.y, v0.z, v0.w, v1.x, v1.y, v1.z, v1.w};
#pragma unroll
            for (int i = 0; i < 4; i++)
#pragma unroll
                for (int j = 0; j < 8; j++) O[i][j] += p[i] * v[j];
        }
        __syncthreads();
    }

    // write out: [N, 256] at head offset
#pragma unroll
    for (int i = 0; i < 4; i++) {
        float rcp = 1.0f / l[i];
#pragma unroll
        for (int j = 0; j < 8; j++)
            out[(size_t)(n0 + r0 + i) * HD + hh * 64 + d0 + j] = O[i][j] * rcp;
    }
}

// ---------------- symmetrize: out = 0.5*(delta + delta^T) ----------------
__global__ void sym_kernel(const float* __restrict__ delta, float* __restrict__ out) {
    __shared__ float t[32][33];
    int i0 = blockIdx.y * 32;
    int j0 = blockIdx.x * 32;
    int tx = threadIdx.x, ty = threadIdx.y;
    // load transposed tile (coalesced)
    t[ty][tx] = delta[(size_t)(j0 + ty) * NN + i0 + tx];
    __syncthreads();
    int i = i0 + ty, j = j0 + tx;
    out[(size_t)i * NN + j] = 0.5f * (delta[(size_t)i * NN + j] + t[tx][ty]);
}

// ---------------- host side ----------------
static inline void run_gemm(const float* A, const float* B, const float* bias, float* C,
                            int M, int N, int K, bool relu,
                            const float* R1 = nullptr, float s1 = 0.f,
                            const float* R2 = nullptr, float s2 = 0.f)
{
    dim3 grid(N / 64, M / 64);
    if (relu)
        gemm_nt<true><<<grid, 128>>>(A, B, bias, C, M, N, K, R1, s1, R2, s2);
    else
        gemm_nt<false><<<grid, 128>>>(A, B, bias, C, M, N, K, R1, s1, R2, s2);
}

extern "C" void kernel_launch(void* const* d_in, const int* in_sizes, int n_in,
                              void* d_out, int out_size)
{
    const float* x     = (const float*)d_in[0];
    const int*   ei    = (const int*)d_in[1];
    const int*   src   = ei;
    const int*   dst   = ei + EE;
    const float* pre_w = (const float*)d_in[2];
    const float* pre_b = (const float*)d_in[3];
    // per-layer weights: base 4 (g1) and 14 (g2)
    const float* mlp_w1 = (const float*)d_in[24];
    const float* mlp_b1 = (const float*)d_in[25];
    const float* mlp_w2 = (const float*)d_in[26];
    const float* mlp_b2 = (const float*)d_in[27];

    float *h, *t1, *gcn, *qkv, *att, *outb, *ffn1, *a2, *delta, *deg, *dinv;
    cudaGetSymbolAddress((void**)&h,     g_h);
    cudaGetSymbolAddress((void**)&t1,    g_t1);
    cudaGetSymbolAddress((void**)&gcn,   g_gcn);
    cudaGetSymbolAddress((void**)&qkv,   g_qkv);
    cudaGetSymbolAddress((void**)&att,   g_att);
    cudaGetSymbolAddress((void**)&outb,  g_out);
    cudaGetSymbolAddress((void**)&ffn1,  g_ffn1);
    cudaGetSymbolAddress((void**)&a2,    g_a2);
    cudaGetSymbolAddress((void**)&delta, g_delta);
    cudaGetSymbolAddress((void**)&deg,   g_deg);
    cudaGetSymbolAddress((void**)&dinv,  g_dinv);

    // h = relu(x @ pre_w^T + pre_b)
    run_gemm(x, pre_w, pre_b, h, NN, HD, IND, true);

    // degree / normalization (recomputed each call; deterministic)
    deg_init_k<<<NN / 256, 256>>>(deg);
    deg_edge_k<<<EE / 256, 256>>>(dst, deg);
    dinv_k<<<NN / 256, 256>>>(deg, dinv);

    for (int L = 0; L < 2; L++) {
        int b = 4 + L * 10;
        const float* gcn_w = (const float*)d_in[b + 0];
        const float* gcn_b = (const float*)d_in[b + 1];
        const float* in_w  = (const float*)d_in[b + 2];
        const float* in_b  = (const float*)d_in[b + 3];
        const float* out_w = (const float*)d_in[b + 4];
        const float* out_b = (const float*)d_in[b + 5];
        const float* w1    = (const float*)d_in[b + 6];
        const float* b1    = (const float*)d_in[b + 7];
        const float* w2    = (const float*)d_in[b + 8];
        const float* b2    = (const float*)d_in[b + 9];

        // GCN branch: t1 = h @ gcn_w^T ; gcn = D^-1/2 (A+I) D^-1/2 t1 + gcn_b
        run_gemm(h, gcn_w, nullptr, t1, NN, HD, HD, false);
        gcn_init_k<<<NN, HD>>>(t1, dinv, gcn_b, gcn);
        gcn_edge_k<<<EE, HD>>>(t1, src, dst, dinv, gcn);

        // attention branch
        run_gemm(h, in_w, in_b, qkv, NN, 3 * HD, HD, false);
        attn_kernel<<<dim3(NN / 64, 4), 128>>>(qkv, att);
        // outb = att @ out_w^T + out_b + gcn + 2*h   (= h1 + h2)
        run_gemm(att, out_w, out_b, outb, NN, HD, HD, false, gcn, 1.0f, h, 2.0f);

        // FFN + residual + outer relu -> new h
        run_gemm(outb, w1, b1, ffn1, NN, 2 * HD, HD, true);
        run_gemm(ffn1, w2, b2, h, NN, HD, 2 * HD, true, outb, 1.0f);
    }

    // readout
    run_gemm(h, mlp_w1, mlp_b1, a2, NN, HD, HD, true);
    run_gemm(a2, mlp_w2, mlp_b2, delta, NN, NN, HD, false);
    sym_kernel<<<dim3(NN / 32, NN / 32), dim3(32, 32)>>>(delta, (float*)d_out);
}

// round 11
// speedup vs baseline: 4.5317x; 4.5317x over previous
#include <cuda_runtime.h>
#include <cuda_fp16.h>
#include <math.h>
#include <stdint.h>

#define NN 4096
#define EE 65536
#define IND 128
#define HD 256

// ---------------- fp32 scratch ----------------
__device__ float g_h[NN * HD];
__device__ float g_t1[NN * HD];
__device__ float g_gcn[NN * HD];
__device__ float g_out[NN * HD];
__device__ float g_delta[(size_t)NN * NN];
__device__ float g_deg[NN];
__device__ float g_dinv[NN];

// ---------------- fp16 scratch ----------------
__device__ __half g_x16[NN * IND];
__device__ __half g_h16[NN * HD];
__device__ __half g_qkv16[NN * 3 * HD];
__device__ __half g_att16[NN * HD];
__device__ __half g_out16[NN * HD];
__device__ __half g_ffn16[NN * 2 * HD];
__device__ __half g_a216[NN * HD];
// fp16 weights
__device__ __half g_wpre[HD * IND];
__device__ __half g_wgcn[2][HD * HD];
__device__ __half g_win[2][3 * HD * HD];
__device__ __half g_wout[2][HD * HD];
__device__ __half g_w1[2][2 * HD * HD];
__device__ __half g_w2[2][2 * HD * HD];
__device__ __half g_wm1[HD * HD];
__device__ __half g_wm2[NN * HD];

// ---------------- mma helpers ----------------
__device__ __forceinline__ void ldsm_x4(uint32_t* r, const __half* p) {
    uint32_t a = (uint32_t)__cvta_generic_to_shared(p);
    asm volatile("ldmatrix.sync.aligned.m8n8.x4.shared.b16 {%0,%1,%2,%3}, [%4];"
                 : "=r"(r[0]), "=r"(r[1]), "=r"(r[2]), "=r"(r[3]) : "r"(a));
}
__device__ __forceinline__ void ldsm_x4_t(uint32_t* r, const __half* p) {
    uint32_t a = (uint32_t)__cvta_generic_to_shared(p);
    asm volatile("ldmatrix.sync.aligned.m8n8.x4.trans.shared.b16 {%0,%1,%2,%3}, [%4];"
                 : "=r"(r[0]), "=r"(r[1]), "=r"(r[2]), "=r"(r[3]) : "r"(a));
}
__device__ __forceinline__ void mma16816(float* c, const uint32_t* a,
                                         uint32_t b0, uint32_t b1) {
    asm volatile("mma.sync.aligned.m16n8k16.row.col.f32.f16.f16.f32 "
                 "{%0,%1,%2,%3},{%4,%5,%6,%7},{%8,%9},{%0,%1,%2,%3};"
                 : "+f"(c[0]), "+f"(c[1]), "+f"(c[2]), "+f"(c[3])
                 : "r"(a[0]), "r"(a[1]), "r"(a[2]), "r"(a[3]), "r"(b0), "r"(b1));
}
__device__ __forceinline__ uint32_t packh2(float x, float y) {
    __half2 h = __floats2half2_rn(x, y);
    return *(uint32_t*)&h;
}

// ---------------- batched f32 -> f16 convert ----------------
struct CvtJob { const float* src; __half* dst; int n; };
struct CvtJobs { CvtJob j[16]; int cnt; };
__global__ void cvt_all_k(CvtJobs jobs) {
    int t = blockIdx.x * blockDim.x + threadIdx.x;
    int stride = gridDim.x * blockDim.x;
    for (int k = 0; k < jobs.cnt; k++) {
        int n4 = jobs.j[k].n >> 2;
        const float4* s = (const float4*)jobs.j[k].src;
        __half2* d = (__half2*)jobs.j[k].dst;
        for (int i = t; i < n4; i += stride) {
            float4 v = s[i];
            d[2 * i]     = __floats2half2_rn(v.x, v.y);
            d[2 * i + 1] = __floats2half2_rn(v.z, v.w);
        }
    }
}

// ---------------- fp16 tensor-core NT GEMM ----------------
// C[M,N] = act(A[M,K] @ B[N,K]^T + bias + s1*R1 + s2*R2), optional fp16 copy C16
#define BM 128
#define BN 128
#define BK 32
#define SKS 40  // BK + 8 pad (halfs)

template <bool RELU>
__global__ void __launch_bounds__(256, 1) hgemm_nt(
    const __half* __restrict__ A, const __half* __restrict__ B,
    const float* __restrict__ bias,
    float* __restrict__ C, __half* __restrict__ C16,
    int M, int N, int K,
    const float* __restrict__ R1, float s1,
    const float* __restrict__ R2, float s2)
{
    __shared__ __half As[BM][SKS];
    __shared__ __half Bs[BN][SKS];
    const int tid = threadIdx.x;
    const int bm = blockIdx.y * BM, bn = blockIdx.x * BN;
    const int warp = tid >> 5, lane = tid & 31;
    const int wm = (warp >> 2) * 64, wn = (warp & 3) * 32;

    float acc[4][4][4];
#pragma unroll
    for (int mt = 0; mt < 4; mt++)
#pragma unroll
        for (int nt = 0; nt < 4; nt++)
#pragma unroll
            for (int i = 0; i < 4; i++) acc[mt][nt][i] = 0.f;

    const int r_row[2] = { (tid + 0) >> 2, (tid + 256) >> 2 };
    const int r_seg[2] = { (tid + 0) & 3,  (tid + 256) & 3 };

    uint4 ra[2], rb[2];
    // prefetch tile 0
#pragma unroll
    for (int i = 0; i < 2; i++) {
        ra[i] = *(const uint4*)&A[(size_t)(bm + r_row[i]) * K + r_seg[i] * 8];
        rb[i] = *(const uint4*)&B[(size_t)(bn + r_row[i]) * K + r_seg[i] * 8];
    }
#pragma unroll
    for (int i = 0; i < 2; i++) {
        *(uint4*)&As[r_row[i]][r_seg[i] * 8] = ra[i];
        *(uint4*)&Bs[r_row[i]][r_seg[i] * 8] = rb[i];
    }
    __syncthreads();

    const int KT = K / BK;
    for (int kt = 0; kt < KT; kt++) {
        if (kt + 1 < KT) {
            int k0 = (kt + 1) * BK;
#pragma unroll
            for (int i = 0; i < 2; i++) {
                ra[i] = *(const uint4*)&A[(size_t)(bm + r_row[i]) * K + k0 + r_seg[i] * 8];
                rb[i] = *(const uint4*)&B[(size_t)(bn + r_row[i]) * K + k0 + r_seg[i] * 8];
            }
        }
#pragma unroll
        for (int kk = 0; kk < 2; kk++) {
            uint32_t af[4][4];
#pragma unroll
            for (int mt = 0; mt < 4; mt++)
                ldsm_x4(af[mt], &As[wm + mt * 16 + (lane & 15)][kk * 16 + ((lane >> 4) << 3)]);
            uint32_t bf[2][4];
#pragma unroll
            for (int p = 0; p < 2; p++)
                ldsm_x4(bf[p], &Bs[wn + p * 16 + (lane & 15)][kk * 16 + ((lane >> 4) << 3)]);
            // B fragment pair is {k-lower, k-upper} for one n-octet:
            // regs {bf[p][sub], bf[p][sub+2]} with sub = nt&1
#pragma unroll
            for (int mt = 0; mt < 4; mt++)
#pragma unroll
                for (int nt = 0; nt < 4; nt++)
                    mma16816(acc[mt][nt], af[mt],
                             bf[nt >> 1][nt & 1], bf[nt >> 1][(nt & 1) + 2]);
        }
        __syncthreads();
        if (kt + 1 < KT) {
#pragma unroll
            for (int i = 0; i < 2; i++) {
                *(uint4*)&As[r_row[i]][r_seg[i] * 8] = ra[i];
                *(uint4*)&Bs[r_row[i]][r_seg[i] * 8] = rb[i];
            }
            __syncthreads();
        }
    }

    // epilogue
#pragma unroll
    for (int mt = 0; mt < 4; mt++) {
#pragma unroll
        for (int nt = 0; nt < 4; nt++) {
            int col = bn + wn + nt * 8 + (lane & 3) * 2;
#pragma unroll
            for (int h2 = 0; h2 < 2; h2++) {
                int row = bm + wm + mt * 16 + (lane >> 2) + h2 * 8;
                float v0 = acc[mt][nt][h2 * 2 + 0];
                float v1 = acc[mt][nt][h2 * 2 + 1];
                if (bias) { v0 += bias[col]; v1 += bias[col + 1]; }
                if (R1) { float2 r = *(const float2*)&R1[(size_t)row * N + col]; v0 += s1 * r.x; v1 += s1 * r.y; }
                if (R2) { float2 r = *(const float2*)&R2[(size_t)row * N + col]; v0 += s2 * r.x; v1 += s2 * r.y; }
                if (RELU) { v0 = fmaxf(v0, 0.f); v1 = fmaxf(v1, 0.f); }
                if (C) *(float2*)&C[(size_t)row * N + col] = make_float2(v0, v1);
                if (C16) *(__half2*)&C16[(size_t)row * N + col] = __floats2half2_rn(v0, v1);
            }
        }
    }
}

// ---------------- GCN helpers (fp32) ----------------
__global__ void deg_init_k(float* deg) {
    int i = blockIdx.x * blockDim.x + threadIdx.x;
    if (i < NN) deg[i] = 1.0f;
}
__global__ void deg_edge_k(const int* __restrict__ dst, float* deg) {
    int e = blockIdx.x * blockDim.x + threadIdx.x;
    if (e < EE) atomicAdd(&deg[dst[e]], 1.0f);
}
__global__ void dinv_k(const float* __restrict__ deg, float* dinv) {
    int i = blockIdx.x * blockDim.x + threadIdx.x;
    if (i < NN) dinv[i] = rsqrtf(deg[i]);
}
__global__ void gcn_init_k(const float* __restrict__ t1, const float* __restrict__ dinv,
                           const float* __restrict__ b, float* __restrict__ out) {
    int i = blockIdx.x;
    int c = threadIdx.x;
    float di = dinv[i];
    out[(size_t)i * HD + c] = di * di * t1[(size_t)i * HD + c] + b[c];
}
__global__ void gcn_edge_k(const float* __restrict__ t1, const int* __restrict__ src,
                           const int* __restrict__ dst, const float* __restrict__ dinv,
                           float* __restrict__ out) {
    int e = blockIdx.x;
    int c = threadIdx.x;
    int s = src[e], d = dst[e];
    float coef = dinv[s] * dinv[d];
    atomicAdd(&out[(size_t)d * HD + c], coef * t1[(size_t)s * HD + c]);
}

// ---------------- FA2 attention via mma.sync (fp16 in, fp32 softmax/accum) ----
// grid (NN/64, 4 heads), 128 threads (4 warps, 16 q-rows each)
__global__ void __launch_bounds__(128) attn_mma(const __half* __restrict__ qkv,
                                                __half* __restrict__ att16)
{
    __shared__ __half Qs[64][72];
    __shared__ __half Ks[64][72];
    __shared__ __half Vs[64][72];
    const int n0 = blockIdx.x * 64;
    const int hh = blockIdx.y;
    const int tid = threadIdx.x;
    const int warp = tid >> 5, lane = tid & 31;

    // load Q (64 rows x 64 halfs)
#pragma unroll
    for (int i = 0; i < 4; i++) {
        int li = tid + i * 128;
        int r = li >> 3, seg = li & 7;
        *(uint4*)&Qs[r][seg * 8] =
            *(const uint4*)&qkv[(size_t)(n0 + r) * 768 + hh * 64 + seg * 8];
    }
    __syncthreads();

    uint32_t qf[4][4];
#pragma unroll
    for (int kk = 0; kk < 4; kk++)
        ldsm_x4(qf[kk], &Qs[warp * 16 + (lane & 15)][kk * 16 + ((lane >> 4) << 3)]);

    float o[8][4];
#pragma unroll
    for (int dt = 0; dt < 8; dt++)
#pragma unroll
        for (int i = 0; i < 4; i++) o[dt][i] = 0.f;
    float m0 = -1e30f, m1 = -1e30f, l0 = 0.f, l1 = 0.f;

    for (int j0 = 0; j0 < NN; j0 += 64) {
        __syncthreads();
#pragma unroll
        for (int i = 0; i < 4; i++) {
            int li = tid + i * 128;
            int r = li >> 3, seg = li & 7;
            *(uint4*)&Ks[r][seg * 8] =
                *(const uint4*)&qkv[(size_t)(j0 + r) * 768 + 256 + hh * 64 + seg * 8];
            *(uint4*)&Vs[r][seg * 8] =
                *(const uint4*)&qkv[(size_t)(j0 + r) * 768 + 512 + hh * 64 + seg * 8];
        }
        __syncthreads();

        // S = Q K^T
        float s[8][4];
#pragma unroll
        for (int nt = 0; nt < 8; nt++)
#pragma unroll
            for (int i = 0; i < 4; i++) s[nt][i] = 0.f;
#pragma unroll
        for (int kk = 0; kk < 4; kk++) {
            uint32_t bf[4][4];
#pragma unroll
            for (int p = 0; p < 4; p++)
                ldsm_x4(bf[p], &Ks[p * 16 + (lane & 15)][kk * 16 + ((lane >> 4) << 3)]);
#pragma unroll
            for (int nt = 0; nt < 8; nt++)
                mma16816(s[nt], qf[kk],
                         bf[nt >> 1][nt & 1], bf[nt >> 1][(nt & 1) + 2]);
        }

        // online softmax (rows r = lane>>2 and r+8); scale 1/sqrt(64)
        float mx0 = -1e30f, mx1 = -1e30f;
#pragma unroll
        for (int nt = 0; nt < 8; nt++) {
#pragma unroll
            for (int i = 0; i < 4; i++) s[nt][i] *= 0.125f;
            mx0 = fmaxf(mx0, fmaxf(s[nt][0], s[nt][1]));
            mx1 = fmaxf(mx1, fmaxf(s[nt][2], s[nt][3]));
        }
        mx0 = fmaxf(mx0, __shfl_xor_sync(0xffffffffu, mx0, 1));
        mx0 = fmaxf(mx0, __shfl_xor_sync(0xffffffffu, mx0, 2));
        mx1 = fmaxf(mx1, __shfl_xor_sync(0xffffffffu, mx1, 1));
        mx1 = fmaxf(mx1, __shfl_xor_sync(0xffffffffu, mx1, 2));
        float mn0 = fmaxf(m0, mx0), mn1 = fmaxf(m1, mx1);
        float corr0 = __expf(m0 - mn0), corr1 = __expf(m1 - mn1);
        m0 = mn0; m1 = mn1;
        float ls0 = 0.f, ls1 = 0.f;
#pragma unroll
        for (int nt = 0; nt < 8; nt++) {
            s[nt][0] = __expf(s[nt][0] - mn0);
            s[nt][1] = __expf(s[nt][1] - mn0);
            s[nt][2] = __expf(s[nt][2] - mn1);
            s[nt][3] = __expf(s[nt][3] - mn1);
            ls0 += s[nt][0] + s[nt][1];
            ls1 += s[nt][2] + s[nt][3];
        }
        ls0 += __shfl_xor_sync(0xffffffffu, ls0, 1);
        ls0 += __shfl_xor_sync(0xffffffffu, ls0, 2);
        ls1 += __shfl_xor_sync(0xffffffffu, ls1, 1);
        ls1 += __shfl_xor_sync(0xffffffffu, ls1, 2);
        l0 = l0 * corr0 + ls0;
        l1 = l1 * corr1 + ls1;
#pragma unroll
        for (int dt = 0; dt < 8; dt++) {
            o[dt][0] *= corr0; o[dt][1] *= corr0;
            o[dt][2] *= corr1; o[dt][3] *= corr1;
        }

        // O += P V  (P stays in registers as A fragments)
        // trans-ldmatrix puts the k-split across {m0,m1} -> contiguous pair is correct here
#pragma unroll
        for (int kk2 = 0; kk2 < 4; kk2++) {
            uint32_t pa[4];
            pa[0] = packh2(s[2 * kk2][0], s[2 * kk2][1]);
            pa[1] = packh2(s[2 * kk2][2], s[2 * kk2][3]);
            pa[2] = packh2(s[2 * kk2 + 1][0], s[2 * kk2 + 1][1]);
            pa[3] = packh2(s[2 * kk2 + 1][2], s[2 * kk2 + 1][3]);
            uint32_t vf[4][4];
#pragma unroll
            for (int p = 0; p < 4; p++)
                ldsm_x4_t(vf[p], &Vs[kk2 * 16 + (lane & 15)][p * 16 + ((lane >> 4) << 3)]);
#pragma unroll
            for (int dt = 0; dt < 8; dt++)
                mma16816(o[dt], pa,
                         vf[dt >> 1][(dt & 1) * 2], vf[dt >> 1][(dt & 1) * 2 + 1]);
        }
    }

    float il0 = 1.0f / l0, il1 = 1.0f / l1;
    int qrow = n0 + warp * 16 + (lane >> 2);
#pragma unroll
    for (int dt = 0; dt < 8; dt++) {
        int d = hh * 64 + dt * 8 + (lane & 3) * 2;
        *(__half2*)&att16[(size_t)qrow * HD + d] =
            __floats2half2_rn(o[dt][0] * il0, o[dt][1] * il0);
        *(__half2*)&att16[(size_t)(qrow + 8) * HD + d] =
            __floats2half2_rn(o[dt][2] * il1, o[dt][3] * il1);
    }
}

// ---------------- symmetrize ----------------
__global__ void sym_kernel(const float* __restrict__ delta, float* __restrict__ out) {
    __shared__ float t[32][33];
    int i0 = blockIdx.y * 32;
    int j0 = blockIdx.x * 32;
    int tx = threadIdx.x, ty = threadIdx.y;
    t[ty][tx] = delta[(size_t)(j0 + ty) * NN + i0 + tx];
    __syncthreads();
    int i = i0 + ty, j = j0 + tx;
    out[(size_t)i * NN + j] = 0.5f * (delta[(size_t)i * NN + j] + t[tx][ty]);
}

// ---------------- host side ----------------
static inline void run_hgemm(const __half* A, const __half* B, const float* bias,
                             float* C, __half* C16, int M, int N, int K, bool relu,
                             const float* R1 = nullptr, float s1 = 0.f,
                             const float* R2 = nullptr, float s2 = 0.f)
{
    dim3 grid(N / BN, M / BM);
    if (relu)
        hgemm_nt<true><<<grid, 256>>>(A, B, bias, C, C16, M, N, K, R1, s1, R2, s2);
    else
        hgemm_nt<false><<<grid, 256>>>(A, B, bias, C, C16, M, N, K, R1, s1, R2, s2);
}

extern "C" void kernel_launch(void* const* d_in, const int* in_sizes, int n_in,
                              void* d_out, int out_size)
{
    const float* x     = (const float*)d_in[0];
    const int*   ei    = (const int*)d_in[1];
    const int*   src   = ei;
    const int*   dst   = ei + EE;
    const float* pre_b = (const float*)d_in[3];
    const float* mlp_b1 = (const float*)d_in[25];
    const float* mlp_b2 = (const float*)d_in[27];

    float *h, *t1, *gcn, *outb, *delta, *deg, *dinv;
    cudaGetSymbolAddress((void**)&h,     g_h);
    cudaGetSymbolAddress((void**)&t1,    g_t1);
    cudaGetSymbolAddress((void**)&gcn,   g_gcn);
    cudaGetSymbolAddress((void**)&outb,  g_out);
    cudaGetSymbolAddress((void**)&delta, g_delta);
    cudaGetSymbolAddress((void**)&deg,   g_deg);
    cudaGetSymbolAddress((void**)&dinv,  g_dinv);

    __half *x16, *h16, *qkv16, *att16, *out16, *ffn16, *a216;
    __half *wpre, *wgcn[2], *win[2], *wout[2], *w1h[2], *w2h[2], *wm1, *wm2;
    cudaGetSymbolAddress((void**)&x16,   g_x16);
    cudaGetSymbolAddress((void**)&h16,   g_h16);
    cudaGetSymbolAddress((void**)&qkv16, g_qkv16);
    cudaGetSymbolAddress((void**)&att16, g_att16);
    cudaGetSymbolAddress((void**)&out16, g_out16);
    cudaGetSymbolAddress((void**)&ffn16, g_ffn16);
    cudaGetSymbolAddress((void**)&a216,  g_a216);
    cudaGetSymbolAddress((void**)&wpre,  g_wpre);
    cudaGetSymbolAddress((void**)&wm1,   g_wm1);
    cudaGetSymbolAddress((void**)&wm2,   g_wm2);
    {
        __half* base;
        cudaGetSymbolAddress((void**)&base, g_wgcn); wgcn[0] = base; wgcn[1] = base + HD * HD;
        cudaGetSymbolAddress((void**)&base, g_win);  win[0] = base;  win[1] = base + 3 * HD * HD;
        cudaGetSymbolAddress((void**)&base, g_wout); wout[0] = base; wout[1] = base + HD * HD;
        cudaGetSymbolAddress((void**)&base, g_w1);   w1h[0] = base;  w1h[1] = base + 2 * HD * HD;
        cudaGetSymbolAddress((void**)&base, g_w2);   w2h[0] = base;  w2h[1] = base + 2 * HD * HD;
    }

    // one batched convert: x + all weights
    CvtJobs jobs;
    int c = 0;
    jobs.j[c++] = { x, x16, NN * IND };
    jobs.j[c++] = { (const float*)d_in[2], wpre, HD * IND };
    for (int L = 0; L < 2; L++) {
        int b = 4 + L * 10;
        jobs.j[c++] = { (const float*)d_in[b + 0], wgcn[L], HD * HD };
        jobs.j[c++] = { (const float*)d_in[b + 2], win[L], 3 * HD * HD };
        jobs.j[c++] = { (const float*)d_in[b + 4], wout[L], HD * HD };
        jobs.j[c++] = { (const float*)d_in[b + 6], w1h[L], 2 * HD * HD };
        jobs.j[c++] = { (const float*)d_in[b + 8], w2h[L], 2 * HD * HD };
    }
    jobs.j[c++] = { (const float*)d_in[24], wm1, HD * HD };
    jobs.j[c++] = { (const float*)d_in[26], wm2, NN * HD };
    jobs.cnt = c;
    cvt_all_k<<<264, 256>>>(jobs);

    // h = relu(x @ pre_w^T + pre_b)  -> fp32 h + fp16 h16
    run_hgemm(x16, wpre, pre_b, h, h16, NN, HD, IND, true);

    // degrees
    deg_init_k<<<NN / 256, 256>>>(deg);
    deg_edge_k<<<EE / 256, 256>>>(dst, deg);
    dinv_k<<<NN / 256, 256>>>(deg, dinv);

    for (int L = 0; L < 2; L++) {
        int b = 4 + L * 10;
        const float* gcn_b = (const float*)d_in[b + 1];
        const float* in_b  = (const float*)d_in[b + 3];
        const float* out_b = (const float*)d_in[b + 5];
        const float* b1    = (const float*)d_in[b + 7];
        const float* b2    = (const float*)d_in[b + 9];

        // GCN branch
        run_hgemm(h16, wgcn[L], nullptr, t1, nullptr, NN, HD, HD, false);
        gcn_init_k<<<NN, HD>>>(t1, dinv, gcn_b, gcn);
        gcn_edge_k<<<EE, HD>>>(t1, src, dst, dinv, gcn);

        // attention branch
        run_hgemm(h16, win[L], in_b, nullptr, qkv16, NN, 3 * HD, HD, false);
        attn_mma<<<dim3(NN / 64, 4), 128>>>(qkv16, att16);
        // outb = att @ out_w^T + out_b + gcn + 2*h
        run_hgemm(att16, wout[L], out_b, outb, out16, NN, HD, HD, false,
                  gcn, 1.0f, h, 2.0f);

        // FFN
        run_hgemm(out16, w1h[L], b1, nullptr, ffn16, NN, 2 * HD, HD, true);
        run_hgemm(ffn16, w2h[L], b2, h, h16, NN, HD, 2 * HD, true, outb, 1.0f);
    }

    // readout
    run_hgemm(h16, wm1, mlp_b1, nullptr, a216, NN, HD, HD, true);
    run_hgemm(a216, wm2, mlp_b2, delta, nullptr, NN, NN, HD, false);
    sym_kernel<<<dim3(NN / 32, NN / 32), dim3(32, 32)>>>(delta, (float*)d_out);
}

// round 12
// speedup vs baseline: 5.0980x; 1.1250x over previous
#include <cuda_runtime.h>
#include <cuda_fp16.h>
#include <math.h>
#include <stdint.h>

#define NN 4096
#define EE 65536
#define IND 128
#define HD 256

// ---------------- fp32 scratch ----------------
__device__ float g_h[NN * HD];
__device__ float g_t1[NN * HD];
__device__ float g_gcn[NN * HD];
__device__ float g_out[NN * HD];
__device__ float g_delta[(size_t)NN * NN];
__device__ float g_dinv[NN];
// CSR scratch
__device__ int g_cnt[NN];
__device__ int g_off[NN + 1];
__device__ int g_cur[NN];
__device__ int g_csr_src[EE];

// ---------------- fp16 scratch ----------------
__device__ __half g_x16[NN * IND];
__device__ __half g_h16[NN * HD];
__device__ __half g_qkv16[NN * 3 * HD];
__device__ __half g_att16[NN * HD];
__device__ __half g_out16[NN * HD];
__device__ __half g_ffn16[NN * 2 * HD];
__device__ __half g_a216[NN * HD];
// fp16 weights
__device__ __half g_wpre[HD * IND];
__device__ __half g_wgcn[2][HD * HD];
__device__ __half g_win[2][3 * HD * HD];
__device__ __half g_wout[2][HD * HD];
__device__ __half g_w1[2][2 * HD * HD];
__device__ __half g_w2[2][2 * HD * HD];
__device__ __half g_wm1[HD * HD];
__device__ __half g_wm2[NN * HD];

// ---------------- mma helpers ----------------
__device__ __forceinline__ void ldsm_x4(uint32_t* r, const __half* p) {
    uint32_t a = (uint32_t)__cvta_generic_to_shared(p);
    asm volatile("ldmatrix.sync.aligned.m8n8.x4.shared.b16 {%0,%1,%2,%3}, [%4];"
                 : "=r"(r[0]), "=r"(r[1]), "=r"(r[2]), "=r"(r[3]) : "r"(a));
}
__device__ __forceinline__ void ldsm_x4_t(uint32_t* r, const __half* p) {
    uint32_t a = (uint32_t)__cvta_generic_to_shared(p);
    asm volatile("ldmatrix.sync.aligned.m8n8.x4.trans.shared.b16 {%0,%1,%2,%3}, [%4];"
                 : "=r"(r[0]), "=r"(r[1]), "=r"(r[2]), "=r"(r[3]) : "r"(a));
}
__device__ __forceinline__ void mma16816(float* c, const uint32_t* a,
                                         uint32_t b0, uint32_t b1) {
    asm volatile("mma.sync.aligned.m16n8k16.row.col.f32.f16.f16.f32 "
                 "{%0,%1,%2,%3},{%4,%5,%6,%7},{%8,%9},{%0,%1,%2,%3};"
                 : "+f"(c[0]), "+f"(c[1]), "+f"(c[2]), "+f"(c[3])
                 : "r"(a[0]), "r"(a[1]), "r"(a[2]), "r"(a[3]), "r"(b0), "r"(b1));
}
__device__ __forceinline__ uint32_t packh2(float x, float y) {
    __half2 h = __floats2half2_rn(x, y);
    return *(uint32_t*)&h;
}

// ---------------- batched f32 -> f16 convert ----------------
struct CvtJob { const float* src; __half* dst; int n; };
struct CvtJobs { CvtJob j[16]; int cnt; };
__global__ void cvt_all_k(CvtJobs jobs) {
    int t = blockIdx.x * blockDim.x + threadIdx.x;
    int stride = gridDim.x * blockDim.x;
    for (int k = 0; k < jobs.cnt; k++) {
        int n4 = jobs.j[k].n >> 2;
        const float4* s = (const float4*)jobs.j[k].src;
        __half2* d = (__half2*)jobs.j[k].dst;
        for (int i = t; i < n4; i += stride) {
            float4 v = s[i];
            d[2 * i]     = __floats2half2_rn(v.x, v.y);
            d[2 * i + 1] = __floats2half2_rn(v.z, v.w);
        }
    }
}

// ---------------- fp16 tensor-core NT GEMM ----------------
#define BM 128
#define BN 128
#define BK 32
#define SKS 40  // BK + 8 pad (halfs)

template <bool RELU>
__global__ void __launch_bounds__(256, 1) hgemm_nt(
    const __half* __restrict__ A, const __half* __restrict__ B,
    const float* __restrict__ bias,
    float* __restrict__ C, __half* __restrict__ C16,
    int M, int N, int K,
    const float* __restrict__ R1, float s1,
    const float* __restrict__ R2, float s2)
{
    __shared__ __half As[BM][SKS];
    __shared__ __half Bs[BN][SKS];
    const int tid = threadIdx.x;
    const int bm = blockIdx.y * BM, bn = blockIdx.x * BN;
    const int warp = tid >> 5, lane = tid & 31;
    const int wm = (warp >> 2) * 64, wn = (warp & 3) * 32;

    float acc[4][4][4];
#pragma unroll
    for (int mt = 0; mt < 4; mt++)
#pragma unroll
        for (int nt = 0; nt < 4; nt++)
#pragma unroll
            for (int i = 0; i < 4; i++) acc[mt][nt][i] = 0.f;

    const int r_row[2] = { (tid + 0) >> 2, (tid + 256) >> 2 };
    const int r_seg[2] = { (tid + 0) & 3,  (tid + 256) & 3 };

    uint4 ra[2], rb[2];
#pragma unroll
    for (int i = 0; i < 2; i++) {
        ra[i] = *(const uint4*)&A[(size_t)(bm + r_row[i]) * K + r_seg[i] * 8];
        rb[i] = *(const uint4*)&B[(size_t)(bn + r_row[i]) * K + r_seg[i] * 8];
    }
#pragma unroll
    for (int i = 0; i < 2; i++) {
        *(uint4*)&As[r_row[i]][r_seg[i] * 8] = ra[i];
        *(uint4*)&Bs[r_row[i]][r_seg[i] * 8] = rb[i];
    }
    __syncthreads();

    const int KT = K / BK;
    for (int kt = 0; kt < KT; kt++) {
        if (kt + 1 < KT) {
            int k0 = (kt + 1) * BK;
#pragma unroll
            for (int i = 0; i < 2; i++) {
                ra[i] = *(const uint4*)&A[(size_t)(bm + r_row[i]) * K + k0 + r_seg[i] * 8];
                rb[i] = *(const uint4*)&B[(size_t)(bn + r_row[i]) * K + k0 + r_seg[i] * 8];
            }
        }
#pragma unroll
        for (int kk = 0; kk < 2; kk++) {
            uint32_t af[4][4];
#pragma unroll
            for (int mt = 0; mt < 4; mt++)
                ldsm_x4(af[mt], &As[wm + mt * 16 + (lane & 15)][kk * 16 + ((lane >> 4) << 3)]);
            uint32_t bf[2][4];
#pragma unroll
            for (int p = 0; p < 2; p++)
                ldsm_x4(bf[p], &Bs[wn + p * 16 + (lane & 15)][kk * 16 + ((lane >> 4) << 3)]);
            // B pair = {k-lower, k-upper} of one n-octet: {bf[p][sub], bf[p][sub+2]}
#pragma unroll
            for (int mt = 0; mt < 4; mt++)
#pragma unroll
                for (int nt = 0; nt < 4; nt++)
                    mma16816(acc[mt][nt], af[mt],
                             bf[nt >> 1][nt & 1], bf[nt >> 1][(nt & 1) + 2]);
        }
        __syncthreads();
        if (kt + 1 < KT) {
#pragma unroll
            for (int i = 0; i < 2; i++) {
                *(uint4*)&As[r_row[i]][r_seg[i] * 8] = ra[i];
                *(uint4*)&Bs[r_row[i]][r_seg[i] * 8] = rb[i];
            }
            __syncthreads();
        }
    }

#pragma unroll
    for (int mt = 0; mt < 4; mt++) {
#pragma unroll
        for (int nt = 0; nt < 4; nt++) {
            int col = bn + wn + nt * 8 + (lane & 3) * 2;
#pragma unroll
            for (int h2 = 0; h2 < 2; h2++) {
                int row = bm + wm + mt * 16 + (lane >> 2) + h2 * 8;
                float v0 = acc[mt][nt][h2 * 2 + 0];
                float v1 = acc[mt][nt][h2 * 2 + 1];
                if (bias) { v0 += bias[col]; v1 += bias[col + 1]; }
                if (R1) { float2 r = *(const float2*)&R1[(size_t)row * N + col]; v0 += s1 * r.x; v1 += s1 * r.y; }
                if (R2) { float2 r = *(const float2*)&R2[(size_t)row * N + col]; v0 += s2 * r.x; v1 += s2 * r.y; }
                if (RELU) { v0 = fmaxf(v0, 0.f); v1 = fmaxf(v1, 0.f); }
                if (C) *(float2*)&C[(size_t)row * N + col] = make_float2(v0, v1);
                if (C16) *(__half2*)&C16[(size_t)row * N + col] = __floats2half2_rn(v0, v1);
            }
        }
    }
}

// ---------------- CSR build (once per launch) ----------------
__global__ void cnt_zero_k(int* cnt) {
    int i = blockIdx.x * blockDim.x + threadIdx.x;
    if (i < NN) cnt[i] = 0;
}
__global__ void cnt_edge_k(const int* __restrict__ dst, int* cnt) {
    int e = blockIdx.x * blockDim.x + threadIdx.x;
    if (e < EE) atomicAdd(&cnt[dst[e]], 1);
}
// single block, 1024 threads, 4 nodes each: exclusive scan -> off/cur, dinv
__global__ void __launch_bounds__(1024) scan_k(const int* __restrict__ cnt,
                                               int* off, int* cur, float* dinv) {
    __shared__ int sums[1024];
    int t = threadIdx.x;
    int base = t * 4;
    int c0 = cnt[base], c1 = cnt[base + 1], c2 = cnt[base + 2], c3 = cnt[base + 3];
    int local = c0 + c1 + c2 + c3;
    sums[t] = local;
    __syncthreads();
    for (int s = 1; s < 1024; s <<= 1) {
        int v = (t >= s) ? sums[t - s] : 0;
        __syncthreads();
        sums[t] += v;
        __syncthreads();
    }
    int pre = sums[t] - local;  // exclusive prefix over 4-chunks
    int o0 = pre, o1 = pre + c0, o2 = o1 + c1, o3 = o2 + c2;
    off[base] = o0; off[base + 1] = o1; off[base + 2] = o2; off[base + 3] = o3;
    cur[base] = o0; cur[base + 1] = o1; cur[base + 2] = o2; cur[base + 3] = o3;
    dinv[base]     = rsqrtf((float)c0 + 1.0f);
    dinv[base + 1] = rsqrtf((float)c1 + 1.0f);
    dinv[base + 2] = rsqrtf((float)c2 + 1.0f);
    dinv[base + 3] = rsqrtf((float)c3 + 1.0f);
    if (t == 1023) off[NN] = sums[1023];
}
__global__ void scatter_k(const int* __restrict__ src, const int* __restrict__ dst,
                          int* cur, int* csr_src) {
    int e = blockIdx.x * blockDim.x + threadIdx.x;
    if (e < EE) {
        int d = dst[e];
        int p = atomicAdd(&cur[d], 1);
        csr_src[p] = src[e];
    }
}

// ---------------- GCN gather (no float atomics) ----------------
// one block per dst node, 256 threads = channels; edge list staged in smem
__global__ void __launch_bounds__(256) gcn_gather_k(
    const float* __restrict__ t1, const int* __restrict__ off,
    const int* __restrict__ csr_src, const float* __restrict__ dinv,
    const float* __restrict__ b, float* __restrict__ out)
{
    __shared__ int   ssrc[256];
    __shared__ float scoef[256];
    int d = blockIdx.x;
    int c = threadIdx.x;
    int beg = off[d], end = off[d + 1];
    int n = end - beg;                 // avg 16; Poisson tail << 256
    float dd = dinv[d];
    // stage edge srcs + coefficients in parallel (n <= 256 in practice; loop guards anyway)
    for (int j = c; j < n; j += 256) {
        int s = csr_src[beg + j];
        ssrc[j]  = s;
        scoef[j] = dd * dinv[s];
    }
    __syncthreads();
    float acc = dd * dd * t1[(size_t)d * HD + c] + b[c];
    for (int j = 0; j < n; j++)
        acc += scoef[j] * t1[(size_t)ssrc[j] * HD + c];
    out[(size_t)d * HD + c] = acc;
}

// ---------------- FA2 attention via mma.sync ----------------
__global__ void __launch_bounds__(128) attn_mma(const __half* __restrict__ qkv,
                                                __half* __restrict__ att16)
{
    __shared__ __half Qs[64][72];
    __shared__ __half Ks[64][72];
    __shared__ __half Vs[64][72];
    const int n0 = blockIdx.x * 64;
    const int hh = blockIdx.y;
    const int tid = threadIdx.x;
    const int warp = tid >> 5, lane = tid & 31;

#pragma unroll
    for (int i = 0; i < 4; i++) {
        int li = tid + i * 128;
        int r = li >> 3, seg = li & 7;
        *(uint4*)&Qs[r][seg * 8] =
            *(const uint4*)&qkv[(size_t)(n0 + r) * 768 + hh * 64 + seg * 8];
    }
    __syncthreads();

    uint32_t qf[4][4];
#pragma unroll
    for (int kk = 0; kk < 4; kk++)
        ldsm_x4(qf[kk], &Qs[warp * 16 + (lane & 15)][kk * 16 + ((lane >> 4) << 3)]);

    float o[8][4];
#pragma unroll
    for (int dt = 0; dt < 8; dt++)
#pragma unroll
        for (int i = 0; i < 4; i++) o[dt][i] = 0.f;
    float m0 = -1e30f, m1 = -1e30f, l0 = 0.f, l1 = 0.f;

    for (int j0 = 0; j0 < NN; j0 += 64) {
        __syncthreads();
#pragma unroll
        for (int i = 0; i < 4; i++) {
            int li = tid + i * 128;
            int r = li >> 3, seg = li & 7;
            *(uint4*)&Ks[r][seg * 8] =
                *(const uint4*)&qkv[(size_t)(j0 + r) * 768 + 256 + hh * 64 + seg * 8];
            *(uint4*)&Vs[r][seg * 8] =
                *(const uint4*)&qkv[(size_t)(j0 + r) * 768 + 512 + hh * 64 + seg * 8];
        }
        __syncthreads();

        float s[8][4];
#pragma unroll
        for (int nt = 0; nt < 8; nt++)
#pragma unroll
            for (int i = 0; i < 4; i++) s[nt][i] = 0.f;
#pragma unroll
        for (int kk = 0; kk < 4; kk++) {
            uint32_t bf[4][4];
#pragma unroll
            for (int p = 0; p < 4; p++)
                ldsm_x4(bf[p], &Ks[p * 16 + (lane & 15)][kk * 16 + ((lane >> 4) << 3)]);
#pragma unroll
            for (int nt = 0; nt < 8; nt++)
                mma16816(s[nt], qf[kk],
                         bf[nt >> 1][nt & 1], bf[nt >> 1][(nt & 1) + 2]);
        }

        float mx0 = -1e30f, mx1 = -1e30f;
#pragma unroll
        for (int nt = 0; nt < 8; nt++) {
#pragma unroll
            for (int i = 0; i < 4; i++) s[nt][i] *= 0.125f;
            mx0 = fmaxf(mx0, fmaxf(s[nt][0], s[nt][1]));
            mx1 = fmaxf(mx1, fmaxf(s[nt][2], s[nt][3]));
        }
        mx0 = fmaxf(mx0, __shfl_xor_sync(0xffffffffu, mx0, 1));
        mx0 = fmaxf(mx0, __shfl_xor_sync(0xffffffffu, mx0, 2));
        mx1 = fmaxf(mx1, __shfl_xor_sync(0xffffffffu, mx1, 1));
        mx1 = fmaxf(mx1, __shfl_xor_sync(0xffffffffu, mx1, 2));
        float mn0 = fmaxf(m0, mx0), mn1 = fmaxf(m1, mx1);
        float corr0 = __expf(m0 - mn0), corr1 = __expf(m1 - mn1);
        m0 = mn0; m1 = mn1;
        float ls0 = 0.f, ls1 = 0.f;
#pragma unroll
        for (int nt = 0; nt < 8; nt++) {
            s[nt][0] = __expf(s[nt][0] - mn0);
            s[nt][1] = __expf(s[nt][1] - mn0);
            s[nt][2] = __expf(s[nt][2] - mn1);
            s[nt][3] = __expf(s[nt][3] - mn1);
            ls0 += s[nt][0] + s[nt][1];
            ls1 += s[nt][2] + s[nt][3];
        }
        ls0 += __shfl_xor_sync(0xffffffffu, ls0, 1);
        ls0 += __shfl_xor_sync(0xffffffffu, ls0, 2);
        ls1 += __shfl_xor_sync(0xffffffffu, ls1, 1);
        ls1 += __shfl_xor_sync(0xffffffffu, ls1, 2);
        l0 = l0 * corr0 + ls0;
        l1 = l1 * corr1 + ls1;
#pragma unroll
        for (int dt = 0; dt < 8; dt++) {
            o[dt][0] *= corr0; o[dt][1] *= corr0;
            o[dt][2] *= corr1; o[dt][3] *= corr1;
        }

#pragma unroll
        for (int kk2 = 0; kk2 < 4; kk2++) {
            uint32_t pa[4];
            pa[0] = packh2(s[2 * kk2][0], s[2 * kk2][1]);
            pa[1] = packh2(s[2 * kk2][2], s[2 * kk2][3]);
            pa[2] = packh2(s[2 * kk2 + 1][0], s[2 * kk2 + 1][1]);
            pa[3] = packh2(s[2 * kk2 + 1][2], s[2 * kk2 + 1][3]);
            uint32_t vf[4][4];
#pragma unroll
            for (int p = 0; p < 4; p++)
                ldsm_x4_t(vf[p], &Vs[kk2 * 16 + (lane & 15)][p * 16 + ((lane >> 4) << 3)]);
#pragma unroll
            for (int dt = 0; dt < 8; dt++)
                mma16816(o[dt], pa,
                         vf[dt >> 1][(dt & 1) * 2], vf[dt >> 1][(dt & 1) * 2 + 1]);
        }
    }

    float il0 = 1.0f / l0, il1 = 1.0f / l1;
    int qrow = n0 + warp * 16 + (lane >> 2);
#pragma unroll
    for (int dt = 0; dt < 8; dt++) {
        int d = hh * 64 + dt * 8 + (lane & 3) * 2;
        *(__half2*)&att16[(size_t)qrow * HD + d] =
            __floats2half2_rn(o[dt][0] * il0, o[dt][1] * il0);
        *(__half2*)&att16[(size_t)(qrow + 8) * HD + d] =
            __floats2half2_rn(o[dt][2] * il1, o[dt][3] * il1);
    }
}

// ---------------- symmetrize ----------------
__global__ void sym_kernel(const float* __restrict__ delta, float* __restrict__ out) {
    __shared__ float t[32][33];
    int i0 = blockIdx.y * 32;
    int j0 = blockIdx.x * 32;
    int tx = threadIdx.x, ty = threadIdx.y;
    t[ty][tx] = delta[(size_t)(j0 + ty) * NN + i0 + tx];
    __syncthreads();
    int i = i0 + ty, j = j0 + tx;
    out[(size_t)i * NN + j] = 0.5f * (delta[(size_t)i * NN + j] + t[tx][ty]);
}

// ---------------- host side ----------------
static inline void run_hgemm(const __half* A, const __half* B, const float* bias,
                             float* C, __half* C16, int M, int N, int K, bool relu,
                             const float* R1 = nullptr, float s1 = 0.f,
                             const float* R2 = nullptr, float s2 = 0.f)
{
    dim3 grid(N / BN, M / BM);
    if (relu)
        hgemm_nt<true><<<grid, 256>>>(A, B, bias, C, C16, M, N, K, R1, s1, R2, s2);
    else
        hgemm_nt<false><<<grid, 256>>>(A, B, bias, C, C16, M, N, K, R1, s1, R2, s2);
}

extern "C" void kernel_launch(void* const* d_in, const int* in_sizes, int n_in,
                              void* d_out, int out_size)
{
    const float* x     = (const float*)d_in[0];
    const int*   ei    = (const int*)d_in[1];
    const int*   src   = ei;
    const int*   dst   = ei + EE;
    const float* pre_b = (const float*)d_in[3];
    const float* mlp_b1 = (const float*)d_in[25];
    const float* mlp_b2 = (const float*)d_in[27];

    float *h, *t1, *gcn, *outb, *delta, *dinv;
    int *cnt, *off, *cur, *csr_src;
    cudaGetSymbolAddress((void**)&h,     g_h);
    cudaGetSymbolAddress((void**)&t1,    g_t1);
    cudaGetSymbolAddress((void**)&gcn,   g_gcn);
    cudaGetSymbolAddress((void**)&outb,  g_out);
    cudaGetSymbolAddress((void**)&delta, g_delta);
    cudaGetSymbolAddress((void**)&dinv,  g_dinv);
    cudaGetSymbolAddress((void**)&cnt,     g_cnt);
    cudaGetSymbolAddress((void**)&off,     g_off);
    cudaGetSymbolAddress((void**)&cur,     g_cur);
    cudaGetSymbolAddress((void**)&csr_src, g_csr_src);

    __half *x16, *h16, *qkv16, *att16, *out16, *ffn16, *a216;
    __half *wpre, *wgcn[2], *win[2], *wout[2], *w1h[2], *w2h[2], *wm1, *wm2;
    cudaGetSymbolAddress((void**)&x16,   g_x16);
    cudaGetSymbolAddress((void**)&h16,   g_h16);
    cudaGetSymbolAddress((void**)&qkv16, g_qkv16);
    cudaGetSymbolAddress((void**)&att16, g_att16);
    cudaGetSymbolAddress((void**)&out16, g_out16);
    cudaGetSymbolAddress((void**)&ffn16, g_ffn16);
    cudaGetSymbolAddress((void**)&a216,  g_a216);
    cudaGetSymbolAddress((void**)&wpre,  g_wpre);
    cudaGetSymbolAddress((void**)&wm1,   g_wm1);
    cudaGetSymbolAddress((void**)&wm2,   g_wm2);
    {
        __half* base;
        cudaGetSymbolAddress((void**)&base, g_wgcn); wgcn[0] = base; wgcn[1] = base + HD * HD;
        cudaGetSymbolAddress((void**)&base, g_win);  win[0] = base;  win[1] = base + 3 * HD * HD;
        cudaGetSymbolAddress((void**)&base, g_wout); wout[0] = base; wout[1] = base + HD * HD;
        cudaGetSymbolAddress((void**)&base, g_w1);   w1h[0] = base;  w1h[1] = base + 2 * HD * HD;
        cudaGetSymbolAddress((void**)&base, g_w2);   w2h[0] = base;  w2h[1] = base + 2 * HD * HD;
    }

    // one batched convert: x + all weights
    CvtJobs jobs;
    int c = 0;
    jobs.j[c++] = { x, x16, NN * IND };
    jobs.j[c++] = { (const float*)d_in[2], wpre, HD * IND };
    for (int L = 0; L < 2; L++) {
        int b = 4 + L * 10;
        jobs.j[c++] = { (const float*)d_in[b + 0], wgcn[L], HD * HD };
        jobs.j[c++] = { (const float*)d_in[b + 2], win[L], 3 * HD * HD };
        jobs.j[c++] = { (const float*)d_in[b + 4], wout[L], HD * HD };
        jobs.j[c++] = { (const float*)d_in[b + 6], w1h[L], 2 * HD * HD };
        jobs.j[c++] = { (const float*)d_in[b + 8], w2h[L], 2 * HD * HD };
    }
    jobs.j[c++] = { (const float*)d_in[24], wm1, HD * HD };
    jobs.j[c++] = { (const float*)d_in[26], wm2, NN * HD };
    jobs.cnt = c;
    cvt_all_k<<<264, 256>>>(jobs);

    // h = relu(x @ pre_w^T + pre_b)
    run_hgemm(x16, wpre, pre_b, h, h16, NN, HD, IND, true);

    // CSR build (once; reused by both layers)
    cnt_zero_k<<<NN / 256, 256>>>(cnt);
    cnt_edge_k<<<EE / 256, 256>>>(dst, cnt);
    scan_k<<<1, 1024>>>(cnt, off, cur, dinv);
    scatter_k<<<EE / 256, 256>>>(src, dst, cur, csr_src);

    for (int L = 0; L < 2; L++) {
        int b = 4 + L * 10;
        const float* gcn_b = (const float*)d_in[b + 1];
        const float* in_b  = (const float*)d_in[b + 3];
        const float* out_b = (const float*)d_in[b + 5];
        const float* b1    = (const float*)d_in[b + 7];
        const float* b2    = (const float*)d_in[b + 9];

        // GCN branch: transform then CSR gather (no float atomics)
        run_hgemm(h16, wgcn[L], nullptr, t1, nullptr, NN, HD, HD, false);
        gcn_gather_k<<<NN, HD>>>(t1, off, csr_src, dinv, gcn_b, gcn);

        // attention branch
        run_hgemm(h16, win[L], in_b, nullptr, qkv16, NN, 3 * HD, HD, false);
        attn_mma<<<dim3(NN / 64, 4), 128>>>(qkv16, att16);
        run_hgemm(att16, wout[L], out_b, outb, out16, NN, HD, HD, false,
                  gcn, 1.0f, h, 2.0f);

        // FFN
        run_hgemm(out16, w1h[L], b1, nullptr, ffn16, NN, 2 * HD, HD, true);
        run_hgemm(ffn16, w2h[L], b2, h, h16, NN, HD, 2 * HD, true, outb, 1.0f);
    }

    // readout
    run_hgemm(h16, wm1, mlp_b1, nullptr, a216, NN, HD, HD, true);
    run_hgemm(a216, wm2, mlp_b2, delta, nullptr, NN, NN, HD, false);
    sym_kernel<<<dim3(NN / 32, NN / 32), dim3(32, 32)>>>(delta, (float*)d_out);
}

// round 16
// speedup vs baseline: 6.0143x; 1.1797x over previous
#include <cuda_runtime.h>
#include <cuda_fp16.h>
#include <math.h>
#include <stdint.h>

#define NN 4096
#define EE 65536
#define IND 128
#define HD 256

// ---------------- fp32 scratch ----------------
__device__ float g_h[NN * HD];
__device__ float g_t1[NN * HD];
__device__ float g_gcn[NN * HD];
__device__ float g_out[NN * HD];
__device__ float g_dinv[NN];
// CSR scratch
__device__ int g_cnt[NN];
__device__ int g_off[NN + 1];
__device__ int g_cur[NN];
__device__ int g_csr_src[EE];

// ---------------- fp16 scratch ----------------
__device__ __half g_x16[NN * IND];
__device__ __half g_h16[NN * HD];
__device__ __half g_qkv16[NN * 3 * HD];
__device__ __half g_att16[NN * HD];
__device__ __half g_out16[NN * HD];
__device__ __half g_ffn16[NN * 2 * HD];
__device__ __half g_a216[NN * HD];
// fp16 weights
__device__ __half g_wpre[HD * IND];
__device__ __half g_wgcn[2][HD * HD];
__device__ __half g_win[2][3 * HD * HD];
__device__ __half g_wout[2][HD * HD];
__device__ __half g_w1[2][2 * HD * HD];
__device__ __half g_w2[2][2 * HD * HD];
__device__ __half g_wm1[HD * HD];
__device__ __half g_wm2[NN * HD];

// ---------------- mma helpers ----------------
__device__ __forceinline__ void ldsm_x4(uint32_t* r, const __half* p) {
    uint32_t a = (uint32_t)__cvta_generic_to_shared(p);
    asm volatile("ldmatrix.sync.aligned.m8n8.x4.shared.b16 {%0,%1,%2,%3}, [%4];"
                 : "=r"(r[0]), "=r"(r[1]), "=r"(r[2]), "=r"(r[3]) : "r"(a));
}
__device__ __forceinline__ void ldsm_x4_t(uint32_t* r, const __half* p) {
    uint32_t a = (uint32_t)__cvta_generic_to_shared(p);
    asm volatile("ldmatrix.sync.aligned.m8n8.x4.trans.shared.b16 {%0,%1,%2,%3}, [%4];"
                 : "=r"(r[0]), "=r"(r[1]), "=r"(r[2]), "=r"(r[3]) : "r"(a));
}
__device__ __forceinline__ void mma16816(float* c, const uint32_t* a,
                                         uint32_t b0, uint32_t b1) {
    asm volatile("mma.sync.aligned.m16n8k16.row.col.f32.f16.f16.f32 "
                 "{%0,%1,%2,%3},{%4,%5,%6,%7},{%8,%9},{%0,%1,%2,%3};"
                 : "+f"(c[0]), "+f"(c[1]), "+f"(c[2]), "+f"(c[3])
                 : "r"(a[0]), "r"(a[1]), "r"(a[2]), "r"(a[3]), "r"(b0), "r"(b1));
}
__device__ __forceinline__ uint32_t packh2(float x, float y) {
    __half2 h = __floats2half2_rn(x, y);
    return *(uint32_t*)&h;
}

// ---------------- batched f32 -> f16 convert ----------------
struct CvtJob { const float* src; __half* dst; int n; };
struct CvtJobs { CvtJob j[16]; int cnt; };
__global__ void cvt_all_k(CvtJobs jobs) {
    int t = blockIdx.x * blockDim.x + threadIdx.x;
    int stride = gridDim.x * blockDim.x;
    for (int k = 0; k < jobs.cnt; k++) {
        int n4 = jobs.j[k].n >> 2;
        const float4* s = (const float4*)jobs.j[k].src;
        __half2* d = (__half2*)jobs.j[k].dst;
        for (int i = t; i < n4; i += stride) {
            float4 v = s[i];
            d[2 * i]     = __floats2half2_rn(v.x, v.y);
            d[2 * i + 1] = __floats2half2_rn(v.z, v.w);
        }
    }
}

// ---------------- fp16 tensor-core NT GEMM (128x128 tile) ----------------
#define BM 128
#define BN 128
#define BK 32
#define SKS 40  // BK + 8 pad (halfs)

template <bool RELU>
__global__ void __launch_bounds__(256, 1) hgemm_nt(
    const __half* __restrict__ A, const __half* __restrict__ B,
    const float* __restrict__ bias,
    float* __restrict__ C, __half* __restrict__ C16,
    int M, int N, int K,
    const float* __restrict__ R1, float s1,
    const float* __restrict__ R2, float s2)
{
    __shared__ __half As[BM][SKS];
    __shared__ __half Bs[BN][SKS];
    const int tid = threadIdx.x;
    const int bm = blockIdx.y * BM, bn = blockIdx.x * BN;
    const int warp = tid >> 5, lane = tid & 31;
    const int wm = (warp >> 2) * 64, wn = (warp & 3) * 32;

    float acc[4][4][4];
#pragma unroll
    for (int mt = 0; mt < 4; mt++)
#pragma unroll
        for (int nt = 0; nt < 4; nt++)
#pragma unroll
            for (int i = 0; i < 4; i++) acc[mt][nt][i] = 0.f;

    const int r_row[2] = { (tid + 0) >> 2, (tid + 256) >> 2 };
    const int r_seg[2] = { (tid + 0) & 3,  (tid + 256) & 3 };

    uint4 ra[2], rb[2];
#pragma unroll
    for (int i = 0; i < 2; i++) {
        ra[i] = *(const uint4*)&A[(size_t)(bm + r_row[i]) * K + r_seg[i] * 8];
        rb[i] = *(const uint4*)&B[(size_t)(bn + r_row[i]) * K + r_seg[i] * 8];
    }
#pragma unroll
    for (int i = 0; i < 2; i++) {
        *(uint4*)&As[r_row[i]][r_seg[i] * 8] = ra[i];
        *(uint4*)&Bs[r_row[i]][r_seg[i] * 8] = rb[i];
    }
    __syncthreads();

    const int KT = K / BK;
    for (int kt = 0; kt < KT; kt++) {
        if (kt + 1 < KT) {
            int k0 = (kt + 1) * BK;
#pragma unroll
            for (int i = 0; i < 2; i++) {
                ra[i] = *(const uint4*)&A[(size_t)(bm + r_row[i]) * K + k0 + r_seg[i] * 8];
                rb[i] = *(const uint4*)&B[(size_t)(bn + r_row[i]) * K + k0 + r_seg[i] * 8];
            }
        }
#pragma unroll
        for (int kk = 0; kk < 2; kk++) {
            uint32_t af[4][4];
#pragma unroll
            for (int mt = 0; mt < 4; mt++)
                ldsm_x4(af[mt], &As[wm + mt * 16 + (lane & 15)][kk * 16 + ((lane >> 4) << 3)]);
            uint32_t bf[2][4];
#pragma unroll
            for (int p = 0; p < 2; p++)
                ldsm_x4(bf[p], &Bs[wn + p * 16 + (lane & 15)][kk * 16 + ((lane >> 4) << 3)]);
#pragma unroll
            for (int mt = 0; mt < 4; mt++)
#pragma unroll
                for (int nt = 0; nt < 4; nt++)
                    mma16816(acc[mt][nt], af[mt],
                             bf[nt >> 1][nt & 1], bf[nt >> 1][(nt & 1) + 2]);
        }
        __syncthreads();
        if (kt + 1 < KT) {
#pragma unroll
            for (int i = 0; i < 2; i++) {
                *(uint4*)&As[r_row[i]][r_seg[i] * 8] = ra[i];
                *(uint4*)&Bs[r_row[i]][r_seg[i] * 8] = rb[i];
            }
            __syncthreads();
        }
    }

#pragma unroll
    for (int mt = 0; mt < 4; mt++) {
#pragma unroll
        for (int nt = 0; nt < 4; nt++) {
            int col = bn + wn + nt * 8 + (lane & 3) * 2;
#pragma unroll
            for (int h2 = 0; h2 < 2; h2++) {
                int row = bm + wm + mt * 16 + (lane >> 2) + h2 * 8;
                float v0 = acc[mt][nt][h2 * 2 + 0];
                float v1 = acc[mt][nt][h2 * 2 + 1];
                if (bias) { v0 += bias[col]; v1 += bias[col + 1]; }
                if (R1) { float2 r = *(const float2*)&R1[(size_t)row * N + col]; v0 += s1 * r.x; v1 += s1 * r.y; }
                if (R2) { float2 r = *(const float2*)&R2[(size_t)row * N + col]; v0 += s2 * r.x; v1 += s2 * r.y; }
                if (RELU) { v0 = fmaxf(v0, 0.f); v1 = fmaxf(v1, 0.f); }
                if (C) *(float2*)&C[(size_t)row * N + col] = make_float2(v0, v1);
                if (C16) *(__half2*)&C16[(size_t)row * N + col] = __floats2half2_rn(v0, v1);
            }
        }
    }
}

// ---------------- fp16 NT GEMM, 64x128 tile (better fill for N=256) ---------
template <bool RELU>
__global__ void __launch_bounds__(256, 1) hgemm_nt64(
    const __half* __restrict__ A, const __half* __restrict__ B,
    const float* __restrict__ bias,
    float* __restrict__ C, __half* __restrict__ C16,
    int M, int N, int K,
    const float* __restrict__ R1, float s1,
    const float* __restrict__ R2, float s2)
{
    __shared__ __half As[64][SKS];
    __shared__ __half Bs[BN][SKS];
    const int tid = threadIdx.x;
    const int bm = blockIdx.y * 64, bn = blockIdx.x * BN;
    const int warp = tid >> 5, lane = tid & 31;
    const int wm = (warp >> 2) * 32, wn = (warp & 3) * 32;

    float acc[2][4][4];
#pragma unroll
    for (int mt = 0; mt < 2; mt++)
#pragma unroll
        for (int nt = 0; nt < 4; nt++)
#pragma unroll
            for (int i = 0; i < 4; i++) acc[mt][nt][i] = 0.f;

    const int a_row = tid >> 2, a_seg = tid & 3;               // 64x32: 1/thread
    const int r_row[2] = { (tid + 0) >> 2, (tid + 256) >> 2 }; // B 128x32: 2/thread
    const int r_seg[2] = { (tid + 0) & 3,  (tid + 256) & 3 };

    uint4 ra, rb[2];
    ra = *(const uint4*)&A[(size_t)(bm + a_row) * K + a_seg * 8];
#pragma unroll
    for (int i = 0; i < 2; i++)
        rb[i] = *(const uint4*)&B[(size_t)(bn + r_row[i]) * K + r_seg[i] * 8];
    *(uint4*)&As[a_row][a_seg * 8] = ra;
#pragma unroll
    for (int i = 0; i < 2; i++)
        *(uint4*)&Bs[r_row[i]][r_seg[i] * 8] = rb[i];
    __syncthreads();

    const int KT = K / BK;
    for (int kt = 0; kt < KT; kt++) {
        if (kt + 1 < KT) {
            int k0 = (kt + 1) * BK;
            ra = *(const uint4*)&A[(size_t)(bm + a_row) * K + k0 + a_seg * 8];
#pragma unroll
            for (int i = 0; i < 2; i++)
                rb[i] = *(const uint4*)&B[(size_t)(bn + r_row[i]) * K + k0 + r_seg[i] * 8];
        }
#pragma unroll
        for (int kk = 0; kk < 2; kk++) {
            uint32_t af[2][4];
#pragma unroll
            for (int mt = 0; mt < 2; mt++)
                ldsm_x4(af[mt], &As[wm + mt * 16 + (lane & 15)][kk * 16 + ((lane >> 4) << 3)]);
            uint32_t bf[2][4];
#pragma unroll
            for (int p = 0; p < 2; p++)
                ldsm_x4(bf[p], &Bs[wn + p * 16 + (lane & 15)][kk * 16 + ((lane >> 4) << 3)]);
#pragma unroll
            for (int mt = 0; mt < 2; mt++)
#pragma unroll
                for (int nt = 0; nt < 4; nt++)
                    mma16816(acc[mt][nt], af[mt],
                             bf[nt >> 1][nt & 1], bf[nt >> 1][(nt & 1) + 2]);
        }
        __syncthreads();
        if (kt + 1 < KT) {
            *(uint4*)&As[a_row][a_seg * 8] = ra;
#pragma unroll
            for (int i = 0; i < 2; i++)
                *(uint4*)&Bs[r_row[i]][r_seg[i] * 8] = rb[i];
            __syncthreads();
        }
    }

#pragma unroll
    for (int mt = 0; mt < 2; mt++) {
#pragma unroll
        for (int nt = 0; nt < 4; nt++) {
            int col = bn + wn + nt * 8 + (lane & 3) * 2;
#pragma unroll
            for (int h2 = 0; h2 < 2; h2++) {
                int row = bm + wm + mt * 16 + (lane >> 2) + h2 * 8;
                float v0 = acc[mt][nt][h2 * 2 + 0];
                float v1 = acc[mt][nt][h2 * 2 + 1];
                if (bias) { v0 += bias[col]; v1 += bias[col + 1]; }
                if (R1) { float2 r = *(const float2*)&R1[(size_t)row * N + col]; v0 += s1 * r.x; v1 += s1 * r.y; }
                if (R2) { float2 r = *(const float2*)&R2[(size_t)row * N + col]; v0 += s2 * r.x; v1 += s2 * r.y; }
                if (RELU) { v0 = fmaxf(v0, 0.f); v1 = fmaxf(v1, 0.f); }
                if (C) *(float2*)&C[(size_t)row * N + col] = make_float2(v0, v1);
                if (C16) *(__half2*)&C16[(size_t)row * N + col] = __floats2half2_rn(v0, v1);
            }
        }
    }
}

// ---------------- fused symmetric readout -----------------------------------
// out[i,j] = 0.5*(a2_i . w_j + a2_j . w_i) + 0.5*(b[j] + b[i])
// One CTA per triangle pair; double-mma into one accumulator; writes tile
// (bi,bj) coalesced + tile (bj,bi) via smem transpose.
// T row stride = 132 floats (528 B): 16B-aligned rows (float4-safe) and
// conflict-free banks for both the scalar writes and the float4 row reads.
#define TST 132

__global__ void __launch_bounds__(256, 1) sym_gemm(
    const __half* __restrict__ A2, const __half* __restrict__ W,
    const float* __restrict__ bias, float* __restrict__ out)
{
    extern __shared__ char dynsmem[];
    __half (*Ai)[SKS] = (__half(*)[SKS])(dynsmem);
    __half (*Wj)[SKS] = (__half(*)[SKS])(dynsmem + 10240);
    __half (*Wi)[SKS] = (__half(*)[SKS])(dynsmem + 20480);
    __half (*Aj)[SKS] = (__half(*)[SKS])(dynsmem + 30720);
    float (*T)[TST]   = (float(*)[TST])(dynsmem);

    // decode triangle pair index t -> (bi, bj), bj <= bi, t = bi*(bi+1)/2 + bj
    int t = blockIdx.x;
    int bi = (int)((sqrtf(8.f * (float)t + 1.f) - 1.f) * 0.5f);
    while ((bi + 1) * (bi + 2) / 2 <= t) bi++;
    while (bi * (bi + 1) / 2 > t) bi--;
    int bj = t - bi * (bi + 1) / 2;

    const int tid = threadIdx.x;
    const int warp = tid >> 5, lane = tid & 31;
    const int wm = (warp >> 2) * 64, wn = (warp & 3) * 32;

    float acc[4][4][4];
#pragma unroll
    for (int mt = 0; mt < 4; mt++)
#pragma unroll
        for (int nt = 0; nt < 4; nt++)
#pragma unroll
            for (int i = 0; i < 4; i++) acc[mt][nt][i] = 0.f;

    const int r_row[2] = { (tid + 0) >> 2, (tid + 256) >> 2 };
    const int r_seg[2] = { (tid + 0) & 3,  (tid + 256) & 3 };
    const size_t ai0 = (size_t)bi * 128 * HD;
    const size_t aj0 = (size_t)bj * 128 * HD;

    uint4 rai[2], rwj[2], rwi[2], raj[2];
#pragma unroll
    for (int i = 0; i < 2; i++) {
        size_t ro = (size_t)r_row[i] * HD + r_seg[i] * 8;
        rai[i] = *(const uint4*)&A2[ai0 + ro];
        rwj[i] = *(const uint4*)&W[aj0 + ro];
        rwi[i] = *(const uint4*)&W[ai0 + ro];
        raj[i] = *(const uint4*)&A2[aj0 + ro];
    }
#pragma unroll
    for (int i = 0; i < 2; i++) {
        *(uint4*)&Ai[r_row[i]][r_seg[i] * 8] = rai[i];
        *(uint4*)&Wj[r_row[i]][r_seg[i] * 8] = rwj[i];
        *(uint4*)&Wi[r_row[i]][r_seg[i] * 8] = rwi[i];
        *(uint4*)&Aj[r_row[i]][r_seg[i] * 8] = raj[i];
    }
    __syncthreads();

    const int KT = HD / BK;  // 8
    for (int kt = 0; kt < KT; kt++) {
        if (kt + 1 < KT) {
            int k0 = (kt + 1) * BK;
#pragma unroll
            for (int i = 0; i < 2; i++) {
                size_t ro = (size_t)r_row[i] * HD + k0 + r_seg[i] * 8;
                rai[i] = *(const uint4*)&A2[ai0 + ro];
                rwj[i] = *(const uint4*)&W[aj0 + ro];
                rwi[i] = *(const uint4*)&W[ai0 + ro];
                raj[i] = *(const uint4*)&A2[aj0 + ro];
            }
        }
#pragma unroll
        for (int kk = 0; kk < 2; kk++) {
            int ko = kk * 16 + ((lane >> 4) << 3);
            uint32_t af[4][4], bf[2][4];
            // pass 1: Ai x Wj^T
#pragma unroll
            for (int mt = 0; mt < 4; mt++)
                ldsm_x4(af[mt], &Ai[wm + mt * 16 + (lane & 15)][ko]);
#pragma unroll
            for (int p = 0; p < 2; p++)
                ldsm_x4(bf[p], &Wj[wn + p * 16 + (lane & 15)][ko]);
#pragma unroll
            for (int mt = 0; mt < 4; mt++)
#pragma unroll
                for (int nt = 0; nt < 4; nt++)
                    mma16816(acc[mt][nt], af[mt],
                             bf[nt >> 1][nt & 1], bf[nt >> 1][(nt & 1) + 2]);
            // pass 2: Wi x Aj^T
#pragma unroll
            for (int mt = 0; mt < 4; mt++)
                ldsm_x4(af[mt], &Wi[wm + mt * 16 + (lane & 15)][ko]);
#pragma unroll
            for (int p = 0; p < 2; p++)
                ldsm_x4(bf[p], &Aj[wn + p * 16 + (lane & 15)][ko]);
#pragma unroll
            for (int mt = 0; mt < 4; mt++)
#pragma unroll
                for (int nt = 0; nt < 4; nt++)
                    mma16816(acc[mt][nt], af[mt],
                             bf[nt >> 1][nt & 1], bf[nt >> 1][(nt & 1) + 2]);
        }
        __syncthreads();
        if (kt + 1 < KT) {
#pragma unroll
            for (int i = 0; i < 2; i++) {
                *(uint4*)&Ai[r_row[i]][r_seg[i] * 8] = rai[i];
                *(uint4*)&Wj[r_row[i]][r_seg[i] * 8] = rwj[i];
                *(uint4*)&Wi[r_row[i]][r_seg[i] * 8] = rwi[i];
                *(uint4*)&Aj[r_row[i]][r_seg[i] * 8] = raj[i];
            }
            __syncthreads();
        }
    }
    // smem now reusable as T (all operand reads done)
    __syncthreads();

    // epilogue: v = 0.5*acc + 0.5*(b[col]+b[row]); write (bi,bj) + stage transpose
#pragma unroll
    for (int mt = 0; mt < 4; mt++) {
#pragma unroll
        for (int nt = 0; nt < 4; nt++) {
            int lcol = wn + nt * 8 + (lane & 3) * 2;
#pragma unroll
            for (int h2 = 0; h2 < 2; h2++) {
                int lrow = wm + mt * 16 + (lane >> 2) + h2 * 8;
                int grow = bi * 128 + lrow;
                float brow = bias[grow];
                float v0 = 0.5f * acc[mt][nt][h2 * 2 + 0] + 0.5f * (bias[bj * 128 + lcol] + brow);
                float v1 = 0.5f * acc[mt][nt][h2 * 2 + 1] + 0.5f * (bias[bj * 128 + lcol + 1] + brow);
                *(float2*)&out[(size_t)grow * NN + bj * 128 + lcol] = make_float2(v0, v1);
                T[lcol][lrow] = v0;
                T[lcol + 1][lrow] = v1;
            }
        }
    }
    if (bi != bj) {
        __syncthreads();
        // flush transposed tile to (bj, bi): warp w handles cols c = i*8 + w
#pragma unroll
        for (int i = 0; i < 16; i++) {
            int c = i * 8 + warp;
            float4 v = *(float4*)&T[c][lane * 4];
            *(float4*)&out[(size_t)(bj * 128 + c) * NN + bi * 128 + lane * 4] = v;
        }
    }
}

// ---------------- CSR build (once per launch) ----------------
__global__ void cnt_zero_k(int* cnt) {
    int i = blockIdx.x * blockDim.x + threadIdx.x;
    if (i < NN) cnt[i] = 0;
}
__global__ void cnt_edge_k(const int* __restrict__ dst, int* cnt) {
    int e = blockIdx.x * blockDim.x + threadIdx.x;
    if (e < EE) atomicAdd(&cnt[dst[e]], 1);
}
__global__ void __launch_bounds__(1024) scan_k(const int* __restrict__ cnt,
                                               int* off, int* cur, float* dinv) {
    __shared__ int sums[1024];
    int t = threadIdx.x;
    int base = t * 4;
    int c0 = cnt[base], c1 = cnt[base + 1], c2 = cnt[base + 2], c3 = cnt[base + 3];
    int local = c0 + c1 + c2 + c3;
    sums[t] = local;
    __syncthreads();
    for (int s = 1; s < 1024; s <<= 1) {
        int v = (t >= s) ? sums[t - s] : 0;
        __syncthreads();
        sums[t] += v;
        __syncthreads();
    }
    int pre = sums[t] - local;
    int o0 = pre, o1 = pre + c0, o2 = o1 + c1, o3 = o2 + c2;
    off[base] = o0; off[base + 1] = o1; off[base + 2] = o2; off[base + 3] = o3;
    cur[base] = o0; cur[base + 1] = o1; cur[base + 2] = o2; cur[base + 3] = o3;
    dinv[base]     = rsqrtf((float)c0 + 1.0f);
    dinv[base + 1] = rsqrtf((float)c1 + 1.0f);
    dinv[base + 2] = rsqrtf((float)c2 + 1.0f);
    dinv[base + 3] = rsqrtf((float)c3 + 1.0f);
    if (t == 1023) off[NN] = sums[1023];
}
__global__ void scatter_k(const int* __restrict__ src, const int* __restrict__ dst,
                          int* cur, int* csr_src) {
    int e = blockIdx.x * blockDim.x + threadIdx.x;
    if (e < EE) {
        int d = dst[e];
        int p = atomicAdd(&cur[d], 1);
        csr_src[p] = src[e];
    }
}

// ---------------- GCN gather (no float atomics) ----------------
__global__ void __launch_bounds__(256) gcn_gather_k(
    const float* __restrict__ t1, const int* __restrict__ off,
    const int* __restrict__ csr_src, const float* __restrict__ dinv,
    const float* __restrict__ b, float* __restrict__ out)
{
    __shared__ int   ssrc[256];
    __shared__ float scoef[256];
    int d = blockIdx.x;
    int c = threadIdx.x;
    int beg = off[d], end = off[d + 1];
    int n = end - beg;
    float dd = dinv[d];
    for (int j = c; j < n; j += 256) {
        int s = csr_src[beg + j];
        ssrc[j]  = s;
        scoef[j] = dd * dinv[s];
    }
    __syncthreads();
    float acc = dd * dd * t1[(size_t)d * HD + c] + b[c];
    for (int j = 0; j < n; j++)
        acc += scoef[j] * t1[(size_t)ssrc[j] * HD + c];
    out[(size_t)d * HD + c] = acc;
}

// ---------------- FA2 attention via mma.sync ----------------
__global__ void __launch_bounds__(128) attn_mma(const __half* __restrict__ qkv,
                                                __half* __restrict__ att16)
{
    __shared__ __half Qs[64][72];
    __shared__ __half Ks[64][72];
    __shared__ __half Vs[64][72];
    const int n0 = blockIdx.x * 64;
    const int hh = blockIdx.y;
    const int tid = threadIdx.x;
    const int warp = tid >> 5, lane = tid & 31;

#pragma unroll
    for (int i = 0; i < 4; i++) {
        int li = tid + i * 128;
        int r = li >> 3, seg = li & 7;
        *(uint4*)&Qs[r][seg * 8] =
            *(const uint4*)&qkv[(size_t)(n0 + r) * 768 + hh * 64 + seg * 8];
    }
    __syncthreads();

    uint32_t qf[4][4];
#pragma unroll
    for (int kk = 0; kk < 4; kk++)
        ldsm_x4(qf[kk], &Qs[warp * 16 + (lane & 15)][kk * 16 + ((lane >> 4) << 3)]);

    float o[8][4];
#pragma unroll
    for (int dt = 0; dt < 8; dt++)
#pragma unroll
        for (int i = 0; i < 4; i++) o[dt][i] = 0.f;
    float m0 = -1e30f, m1 = -1e30f, l0 = 0.f, l1 = 0.f;

    for (int j0 = 0; j0 < NN; j0 += 64) {
        __syncthreads();
#pragma unroll
        for (int i = 0; i < 4; i++) {
            int li = tid + i * 128;
            int r = li >> 3, seg = li & 7;
            *(uint4*)&Ks[r][seg * 8] =
                *(const uint4*)&qkv[(size_t)(j0 + r) * 768 + 256 + hh * 64 + seg * 8];
            *(uint4*)&Vs[r][seg * 8] =
                *(const uint4*)&qkv[(size_t)(j0 + r) * 768 + 512 + hh * 64 + seg * 8];
        }
        __syncthreads();

        float s[8][4];
#pragma unroll
        for (int nt = 0; nt < 8; nt++)
#pragma unroll
            for (int i = 0; i < 4; i++) s[nt][i] = 0.f;
#pragma unroll
        for (int kk = 0; kk < 4; kk++) {
            uint32_t bf[4][4];
#pragma unroll
            for (int p = 0; p < 4; p++)
                ldsm_x4(bf[p], &Ks[p * 16 + (lane & 15)][kk * 16 + ((lane >> 4) << 3)]);
#pragma unroll
            for (int nt = 0; nt < 8; nt++)
                mma16816(s[nt], qf[kk],
                         bf[nt >> 1][nt & 1], bf[nt >> 1][(nt & 1) + 2]);
        }

        float mx0 = -1e30f, mx1 = -1e30f;
#pragma unroll
        for (int nt = 0; nt < 8; nt++) {
#pragma unroll
            for (int i = 0; i < 4; i++) s[nt][i] *= 0.125f;
            mx0 = fmaxf(mx0, fmaxf(s[nt][0], s[nt][1]));
            mx1 = fmaxf(mx1, fmaxf(s[nt][2], s[nt][3]));
        }
        mx0 = fmaxf(mx0, __shfl_xor_sync(0xffffffffu, mx0, 1));
        mx0 = fmaxf(mx0, __shfl_xor_sync(0xffffffffu, mx0, 2));
        mx1 = fmaxf(mx1, __shfl_xor_sync(0xffffffffu, mx1, 1));
        mx1 = fmaxf(mx1, __shfl_xor_sync(0xffffffffu, mx1, 2));
        float mn0 = fmaxf(m0, mx0), mn1 = fmaxf(m1, mx1);
        float corr0 = __expf(m0 - mn0), corr1 = __expf(m1 - mn1);
        m0 = mn0; m1 = mn1;
        float ls0 = 0.f, ls1 = 0.f;
#pragma unroll
        for (int nt = 0; nt < 8; nt++) {
            s[nt][0] = __expf(s[nt][0] - mn0);
            s[nt][1] = __expf(s[nt][1] - mn0);
            s[nt][2] = __expf(s[nt][2] - mn1);
            s[nt][3] = __expf(s[nt][3] - mn1);
            ls0 += s[nt][0] + s[nt][1];
            ls1 += s[nt][2] + s[nt][3];
        }
        ls0 += __shfl_xor_sync(0xffffffffu, ls0, 1);
        ls0 += __shfl_xor_sync(0xffffffffu, ls0, 2);
        ls1 += __shfl_xor_sync(0xffffffffu, ls1, 1);
        ls1 += __shfl_xor_sync(0xffffffffu, ls1, 2);
        l0 = l0 * corr0 + ls0;
        l1 = l1 * corr1 + ls1;
#pragma unroll
        for (int dt = 0; dt < 8; dt++) {
            o[dt][0] *= corr0; o[dt][1] *= corr0;
            o[dt][2] *= corr1; o[dt][3] *= corr1;
        }

#pragma unroll
        for (int kk2 = 0; kk2 < 4; kk2++) {
            uint32_t pa[4];
            pa[0] = packh2(s[2 * kk2][0], s[2 * kk2][1]);
            pa[1] = packh2(s[2 * kk2][2], s[2 * kk2][3]);
            pa[2] = packh2(s[2 * kk2 + 1][0], s[2 * kk2 + 1][1]);
            pa[3] = packh2(s[2 * kk2 + 1][2], s[2 * kk2 + 1][3]);
            uint32_t vf[4][4];
#pragma unroll
            for (int p = 0; p < 4; p++)
                ldsm_x4_t(vf[p], &Vs[kk2 * 16 + (lane & 15)][p * 16 + ((lane >> 4) << 3)]);
#pragma unroll
            for (int dt = 0; dt < 8; dt++)
                mma16816(o[dt], pa,
                         vf[dt >> 1][(dt & 1) * 2], vf[dt >> 1][(dt & 1) * 2 + 1]);
        }
    }

    float il0 = 1.0f / l0, il1 = 1.0f / l1;
    int qrow = n0 + warp * 16 + (lane >> 2);
#pragma unroll
    for (int dt = 0; dt < 8; dt++) {
        int d = hh * 64 + dt * 8 + (lane & 3) * 2;
        *(__half2*)&att16[(size_t)qrow * HD + d] =
            __floats2half2_rn(o[dt][0] * il0, o[dt][1] * il0);
        *(__half2*)&att16[(size_t)(qrow + 8) * HD + d] =
            __floats2half2_rn(o[dt][2] * il1, o[dt][3] * il1);
    }
}

// ---------------- host side ----------------
static inline void run_hgemm(const __half* A, const __half* B, const float* bias,
                             float* C, __half* C16, int M, int N, int K, bool relu,
                             const float* R1 = nullptr, float s1 = 0.f,
                             const float* R2 = nullptr, float s2 = 0.f)
{
    if (N == 256) {  // small-N: 64-row tiles double the CTA count (SM fill)
        dim3 grid(N / BN, M / 64);
        if (relu)
            hgemm_nt64<true><<<grid, 256>>>(A, B, bias, C, C16, M, N, K, R1, s1, R2, s2);
        else
            hgemm_nt64<false><<<grid, 256>>>(A, B, bias, C, C16, M, N, K, R1, s1, R2, s2);
    } else {
        dim3 grid(N / BN, M / BM);
        if (relu)
            hgemm_nt<true><<<grid, 256>>>(A, B, bias, C, C16, M, N, K, R1, s1, R2, s2);
        else
            hgemm_nt<false><<<grid, 256>>>(A, B, bias, C, C16, M, N, K, R1, s1, R2, s2);
    }
}

extern "C" void kernel_launch(void* const* d_in, const int* in_sizes, int n_in,
                              void* d_out, int out_size)
{
    const float* x     = (const float*)d_in[0];
    const int*   ei    = (const int*)d_in[1];
    const int*   src   = ei;
    const int*   dst   = ei + EE;
    const float* pre_b = (const float*)d_in[3];
    const float* mlp_b1 = (const float*)d_in[25];
    const float* mlp_b2 = (const float*)d_in[27];

    float *h, *t1, *gcn, *outb, *dinv;
    int *cnt, *off, *cur, *csr_src;
    cudaGetSymbolAddress((void**)&h,     g_h);
    cudaGetSymbolAddress((void**)&t1,    g_t1);
    cudaGetSymbolAddress((void**)&gcn,   g_gcn);
    cudaGetSymbolAddress((void**)&outb,  g_out);
    cudaGetSymbolAddress((void**)&dinv,  g_dinv);
    cudaGetSymbolAddress((void**)&cnt,     g_cnt);
    cudaGetSymbolAddress((void**)&off,     g_off);
    cudaGetSymbolAddress((void**)&cur,     g_cur);
    cudaGetSymbolAddress((void**)&csr_src, g_csr_src);

    __half *x16, *h16, *qkv16, *att16, *out16, *ffn16, *a216;
    __half *wpre, *wgcn[2], *win[2], *wout[2], *w1h[2], *w2h[2], *wm1, *wm2;
    cudaGetSymbolAddress((void**)&x16,   g_x16);
    cudaGetSymbolAddress((void**)&h16,   g_h16);
    cudaGetSymbolAddress((void**)&qkv16, g_qkv16);
    cudaGetSymbolAddress((void**)&att16, g_att16);
    cudaGetSymbolAddress((void**)&out16, g_out16);
    cudaGetSymbolAddress((void**)&ffn16, g_ffn16);
    cudaGetSymbolAddress((void**)&a216,  g_a216);
    cudaGetSymbolAddress((void**)&wpre,  g_wpre);
    cudaGetSymbolAddress((void**)&wm1,   g_wm1);
    cudaGetSymbolAddress((void**)&wm2,   g_wm2);
    {
        __half* base;
        cudaGetSymbolAddress((void**)&base, g_wgcn); wgcn[0] = base; wgcn[1] = base + HD * HD;
        cudaGetSymbolAddress((void**)&base, g_win);  win[0] = base;  win[1] = base + 3 * HD * HD;
        cudaGetSymbolAddress((void**)&base, g_wout); wout[0] = base; wout[1] = base + HD * HD;
        cudaGetSymbolAddress((void**)&base, g_w1);   w1h[0] = base;  w1h[1] = base + 2 * HD * HD;
        cudaGetSymbolAddress((void**)&base, g_w2);   w2h[0] = base;  w2h[1] = base + 2 * HD * HD;
    }

    static bool attr_set = false;
    if (!attr_set) {
        cudaFuncSetAttribute(sym_gemm, cudaFuncAttributeMaxDynamicSharedMemorySize,
                             TST * 128 * 4);
        attr_set = true;
    }

    // one batched convert: x + all weights
    CvtJobs jobs;
    int c = 0;
    jobs.j[c++] = { x, x16, NN * IND };
    jobs.j[c++] = { (const float*)d_in[2], wpre, HD * IND };
    for (int L = 0; L < 2; L++) {
        int b = 4 + L * 10;
        jobs.j[c++] = { (const float*)d_in[b + 0], wgcn[L], HD * HD };
        jobs.j[c++] = { (const float*)d_in[b + 2], win[L], 3 * HD * HD };
        jobs.j[c++] = { (const float*)d_in[b + 4], wout[L], HD * HD };
        jobs.j[c++] = { (const float*)d_in[b + 6], w1h[L], 2 * HD * HD };
        jobs.j[c++] = { (const float*)d_in[b + 8], w2h[L], 2 * HD * HD };
    }
    jobs.j[c++] = { (const float*)d_in[24], wm1, HD * HD };
    jobs.j[c++] = { (const float*)d_in[26], wm2, NN * HD };
    jobs.cnt = c;
    cvt_all_k<<<264, 256>>>(jobs);

    // h = relu(x @ pre_w^T + pre_b)
    run_hgemm(x16, wpre, pre_b, h, h16, NN, HD, IND, true);

    // CSR build (once; reused by both layers)
    cnt_zero_k<<<NN / 256, 256>>>(cnt);
    cnt_edge_k<<<EE / 256, 256>>>(dst, cnt);
    scan_k<<<1, 1024>>>(cnt, off, cur, dinv);
    scatter_k<<<EE / 256, 256>>>(src, dst, cur, csr_src);

    for (int L = 0; L < 2; L++) {
        int b = 4 + L * 10;
        const float* gcn_b = (const float*)d_in[b + 1];
        const float* in_b  = (const float*)d_in[b + 3];
        const float* out_b = (const float*)d_in[b + 5];
        const float* b1    = (const float*)d_in[b + 7];
        const float* b2    = (const float*)d_in[b + 9];

        // GCN branch
        run_hgemm(h16, wgcn[L], nullptr, t1, nullptr, NN, HD, HD, false);
        gcn_gather_k<<<NN, HD>>>(t1, off, csr_src, dinv, gcn_b, gcn);

        // attention branch
        run_hgemm(h16, win[L], in_b, nullptr, qkv16, NN, 3 * HD, HD, false);
        attn_mma<<<dim3(NN / 64, 4), 128>>>(qkv16, att16);
        run_hgemm(att16, wout[L], out_b, outb, out16, NN, HD, HD, false,
                  gcn, 1.0f, h, 2.0f);

        // FFN
        run_hgemm(out16, w1h[L], b1, nullptr, ffn16, NN, 2 * HD, HD, true);
        run_hgemm(ffn16, w2h[L], b2, h, h16, NN, HD, 2 * HD, true, outb, 1.0f);
    }

    // fused symmetric readout: out = 0.5*(delta + delta^T) without delta scratch
    run_hgemm(h16, wm1, mlp_b1, nullptr, a216, NN, HD, HD, true);
    sym_gemm<<<528, 256, TST * 128 * 4>>>(a216, wm2, mlp_b2, (float*)d_out);
}